// round 10
// baseline (speedup 1.0000x reference)
#include <cuda_runtime.h>
#include <cuda_bf16.h>
#include <cstdint>

#define Bb 128
#define Ss 128
#define ISZ 384
#define HSZ 768
#define GSZ 3072
#define HID (Bb*Ss*HSZ)
#define STATE (Bb*HSZ)
#define NCTAR 96
#define RTHREADS 512

// ---------------- device scratch ----------------
__device__ __nv_bfloat16 g_Umt_hi[GSZ*HSZ];
__device__ __nv_bfloat16 g_Umt_lo[GSZ*HSZ];
__device__ __nv_bfloat16 g_Wmt_hi[GSZ*ISZ];
__device__ __nv_bfloat16 g_Wmt_lo[GSZ*ISZ];
__device__ __nv_bfloat16 g_Xh[Bb*Ss*ISZ];
__device__ __nv_bfloat16 g_Xl[Bb*Ss*ISZ];
__device__ float g_xg[(size_t)Ss*Bb*GSZ];     // [s][b][n] includes bias
__device__ __nv_bfloat16 g_Hh[STATE];         // h bf16 hi [b][k]
__device__ __nv_bfloat16 g_Hl[STATE];         // h bf16 lo [b][k]
__device__ float g_ct[STATE];                 // c0 fp32 [b][j]
__device__ float g_biasp[GSZ];
__device__ unsigned g_cnt;
__device__ volatile unsigned g_epoch;

// ---------------- helpers ----------------
__device__ __forceinline__ uint32_t smem_u32(const void* p) {
    uint32_t a;
    asm("{ .reg .u64 t; cvta.to.shared.u64 t, %1; cvt.u32.u64 %0, t; }" : "=r"(a) : "l"(p));
    return a;
}
__device__ __forceinline__ void ldsm4(uint32_t& r0, uint32_t& r1, uint32_t& r2, uint32_t& r3, uint32_t addr) {
    asm volatile("ldmatrix.sync.aligned.m8n8.x4.shared.b16 {%0,%1,%2,%3}, [%4];"
                 : "=r"(r0), "=r"(r1), "=r"(r2), "=r"(r3) : "r"(addr));
}
__device__ __forceinline__ void mma16816(float* c, const uint32_t* a, uint32_t b0, uint32_t b1) {
    asm volatile("mma.sync.aligned.m16n8k16.row.col.f32.bf16.bf16.f32 "
                 "{%0,%1,%2,%3}, {%4,%5,%6,%7}, {%8,%9}, {%0,%1,%2,%3};"
                 : "+f"(c[0]), "+f"(c[1]), "+f"(c[2]), "+f"(c[3])
                 : "r"(a[0]), "r"(a[1]), "r"(a[2]), "r"(a[3]), "r"(b0), "r"(b1));
}
__device__ __forceinline__ unsigned short bf_hi(float x, float& rem) {
    __nv_bfloat16 h = __float2bfloat16(x);
    rem = x - __bfloat162float(h);
    return __bfloat16_as_ushort(h);
}
__device__ __forceinline__ float fsig(float x)  { return 1.0f / (1.0f + __expf(-x)); }
__device__ __forceinline__ float ftanh(float x) { return 2.0f / (1.0f + __expf(-2.0f * x)) - 1.0f; }

#define CP_ASYNC_CG(dst, src) asm volatile("cp.async.cg.shared.global [%0], [%1], 16;" :: "r"(dst), "l"(src))
#define CP_COMMIT()           asm volatile("cp.async.commit_group;" ::: "memory")
#define CP_WAIT0()            asm volatile("cp.async.wait_group 0;" ::: "memory")

// ================= recur2 SMEM layout =================
#define SB_BHI 0
#define SB_BLO 49152
#define SB_A   98304          /* 2 bufs x (hi 16K + lo 16K) */
#define SB_STG 163840         /* C stage: 128 x 36 floats */
#define SB_CST 182272         /* c state: 128 x 8 floats */
#define SMEM2  186368

// ================= xw_gemm SMEM geometry =================
#define ROWB 272
#define TILEB (128 * ROWB)
#define OFF_A_HI 0u
#define OFF_A_LO 34816u
#define OFF_B_HI 69632u
#define OFF_B_LO 104448u
#define SMEMSZ   139264

__device__ __forceinline__ void mma_tile3(uint32_t sA, uint32_t sB, int lane, int mb, int nb, float c[2][8][4]) {
    uint32_t aBase = sA + (uint32_t)(mb + (lane & 15)) * ROWB + (uint32_t)(lane >> 4) * 16;
    uint32_t bBase = sB + (uint32_t)(nb + ((lane >> 4) << 3) + (lane & 7)) * ROWB + (uint32_t)((lane >> 3) & 1) * 16;
#pragma unroll
    for (int k0 = 0; k0 < 128; k0 += 16) {
        uint32_t ah[2][4], al[2][4];
#pragma unroll
        for (int mi = 0; mi < 2; mi++) {
            uint32_t ao = aBase + (uint32_t)(mi * 16 * ROWB + k0 * 2);
            ldsm4(ah[mi][0], ah[mi][1], ah[mi][2], ah[mi][3], ao);
            ldsm4(al[mi][0], al[mi][1], al[mi][2], al[mi][3], ao + TILEB);
        }
#pragma unroll
        for (int nj = 0; nj < 4; nj++) {
            uint32_t bo = bBase + (uint32_t)(nj * 16 * ROWB + k0 * 2);
            uint32_t bh0, bh1, bh2, bh3, bl0, bl1, bl2, bl3;
            ldsm4(bh0, bh1, bh2, bh3, bo);
            ldsm4(bl0, bl1, bl2, bl3, bo + TILEB);
#pragma unroll
            for (int mi = 0; mi < 2; mi++) {
                mma16816(c[mi][nj * 2],     ah[mi], bh0, bh1);
                mma16816(c[mi][nj * 2 + 1], ah[mi], bh2, bh3);
                mma16816(c[mi][nj * 2],     al[mi], bh0, bh1);
                mma16816(c[mi][nj * 2 + 1], al[mi], bh2, bh3);
                mma16816(c[mi][nj * 2],     ah[mi], bl0, bl1);
                mma16816(c[mi][nj * 2 + 1], ah[mi], bl2, bl3);
            }
        }
    }
}

// ---------------- one-time conversions ----------------
__global__ void convAll(const float* __restrict__ x, const float* __restrict__ h0,
                        const float* __restrict__ c0, const float* __restrict__ W,
                        const float* __restrict__ U, const float* __restrict__ bias,
                        const float* __restrict__ G) {
    int idx = blockIdx.x * blockDim.x + threadIdx.x;
    float rem;
    if (idx == 0) { g_cnt = 0; g_epoch = 0; }
    if (idx < Bb * Ss * ISZ) {
        int f = idx % ISZ, r = idx / ISZ;
        int s = r >> 7, b = r & 127;
        float v = x[((size_t)b * Ss + s) * ISZ + f];
        g_Xh[idx] = __ushort_as_bfloat16(bf_hi(v, rem));
        g_Xl[idx] = __float2bfloat16(rem);
    }
    if (idx < GSZ * HSZ) {
        int n = idx / HSZ, k = idx % HSZ;
        int j = n >> 2, g = n & 3;
        float v = U[(size_t)k * GSZ + g * HSZ + j] * G[(k >> 5) * 24 + (j >> 5)];
        g_Umt_hi[idx] = __ushort_as_bfloat16(bf_hi(v, rem));
        g_Umt_lo[idx] = __float2bfloat16(rem);
    }
    if (idx < GSZ * ISZ) {
        int n = idx / ISZ, k = idx % ISZ;
        int j = n >> 2, g = n & 3;
        float v = W[(size_t)k * GSZ + g * HSZ + j] * G[(k >> 4) * 24 + (j >> 5)];
        g_Wmt_hi[idx] = __ushort_as_bfloat16(bf_hi(v, rem));
        g_Wmt_lo[idx] = __float2bfloat16(rem);
    }
    if (idx < STATE) {
        g_Hh[idx] = __ushort_as_bfloat16(bf_hi(h0[idx], rem));
        g_Hl[idx] = __float2bfloat16(rem);
        g_ct[idx] = c0[idx];
        if (idx < GSZ) g_biasp[idx] = bias[(idx & 3) * HSZ + (idx >> 2)];
    }
}

// keeps recur2 in the 4th-launch ncu capture slot
__global__ void dummyK() {}

// ---------------- input projection ----------------
__global__ void __launch_bounds__(256, 1) xw_gemm() {
    extern __shared__ char smem[];
    const uint32_t sb = smem_u32(smem);
    const int tid = threadIdx.x, wid = tid >> 5, lane = tid & 31;
    const int n0 = blockIdx.x * 128, s = blockIdx.y;

    float c[2][8][4];
#pragma unroll
    for (int i = 0; i < 2; i++)
#pragma unroll
        for (int j = 0; j < 8; j++)
#pragma unroll
            for (int q = 0; q < 4; q++) c[i][j][q] = 0.0f;

    for (int ck = 0; ck < 3; ck++) {
        if (ck) __syncthreads();
        for (int i = tid; i < 8192; i += 256) {
            int ab = i >> 12;
            int hl = (i >> 11) & 1, r = i & 2047, row = r >> 4, blk = r & 15;
            const __nv_bfloat16* src;
            uint32_t dst;
            if (ab == 0) {
                src = (hl ? g_Xl : g_Xh) + (size_t)(s * 128 + row) * ISZ + ck * 128 + blk * 8;
                dst = (hl ? OFF_A_LO : OFF_A_HI);
            } else {
                src = (hl ? g_Wmt_lo : g_Wmt_hi) + (size_t)(n0 + row) * ISZ + ck * 128 + blk * 8;
                dst = (hl ? OFF_B_LO : OFF_B_HI);
            }
            dst += (uint32_t)row * ROWB + (uint32_t)blk * 16;
            *reinterpret_cast<uint4*>(smem + dst) = *reinterpret_cast<const uint4*>(src);
        }
        __syncthreads();
        mma_tile3(sb + OFF_A_HI, sb + OFF_B_HI, lane, (wid & 3) * 32, (wid >> 2) * 64, c);
    }
    {
        const int nb = (wid >> 2) * 64;
        const int col0 = n0 + nb + (lane & 3) * 2;
#pragma unroll
        for (int ni = 0; ni < 8; ni++) {
            float b0 = g_biasp[col0 + ni * 8];
            float b1 = g_biasp[col0 + ni * 8 + 1];
#pragma unroll
            for (int mi = 0; mi < 2; mi++) {
                c[mi][ni][0] += b0; c[mi][ni][1] += b1;
                c[mi][ni][2] += b0; c[mi][ni][3] += b1;
            }
        }
    }
    __syncthreads();
    {
        float* CS = reinterpret_cast<float*>(smem);
        const int mb = (wid & 3) * 32, nb = (wid >> 2) * 64;
        const int r0 = mb + (lane >> 2);
        const int col0 = nb + (lane & 3) * 2;
#pragma unroll
        for (int mi = 0; mi < 2; mi++)
#pragma unroll
            for (int ni = 0; ni < 8; ni++) {
                float* p0 = &CS[(r0 + mi * 16) * 132 + col0 + ni * 8];
                p0[0] = c[mi][ni][0]; p0[1] = c[mi][ni][1];
                float* p1 = &CS[(r0 + mi * 16 + 8) * 132 + col0 + ni * 8];
                p1[0] = c[mi][ni][2]; p1[1] = c[mi][ni][3];
            }
        __syncthreads();
        const int b = tid >> 1, half = tid & 1;
        const float4* src = reinterpret_cast<const float4*>(&CS[b * 132 + half * 64]);
        float4* dst = reinterpret_cast<float4*>(g_xg + (size_t)s * Bb * GSZ + n0 + (size_t)b * GSZ + half * 64);
#pragma unroll
        for (int q = 0; q < 16; q++) dst[q] = src[q];
    }
}

// ---------------- persistent fused recurrence (512 threads, 16 warps) ----------------
__device__ __forceinline__ void issue_chunkA(uint32_t sb, int tid, int kc, int buf) {
#pragma unroll
    for (int q = 0; q < 4; q++) {
        int idx = tid + RTHREADS * q;
        int hl = idx >> 10, r = idx & 1023, b = r >> 3, kb = r & 7;
        const __nv_bfloat16* src = (hl ? g_Hl : g_Hh) + (size_t)b * HSZ + kc * 64 + kb * 8;
        uint32_t dst = sb + SB_A + (uint32_t)buf * 32768u + (uint32_t)hl * 16384u +
                       (uint32_t)b * 128u + (uint32_t)((kb ^ (b & 7)) << 4);
        CP_ASYNC_CG(dst, src);
    }
    CP_COMMIT();
}

__global__ void __launch_bounds__(RTHREADS, 1) recur2(float* __restrict__ out) {
    extern __shared__ char smem[];
    const uint32_t sb = smem_u32(smem);
    const int tid = threadIdx.x, wid = tid >> 5, lane = tid & 31;
    const int nt = blockIdx.x;
    const int n0 = nt * 32;
    const int j0 = nt * 8;

    // B resident (once)
    for (int i = tid; i < 6144; i += RTHREADS) {
        int hl = (i >= 3072);
        int r = hl ? (i - 3072) : i;
        int n = r / 96, kb = r % 96;
        const __nv_bfloat16* src = (hl ? g_Umt_lo : g_Umt_hi) + (size_t)(n0 + n) * HSZ + kb * 8;
        uint32_t dst = (hl ? SB_BLO : SB_BHI) + (uint32_t)n * 1536 + (uint32_t)((kb ^ (n & 7)) << 4);
        *reinterpret_cast<uint4*>(smem + dst) = *reinterpret_cast<const uint4*>(src);
    }
    float* cst = reinterpret_cast<float*>(smem + SB_CST);
    for (int i = tid; i < 1024; i += RTHREADS) {
        int b = i >> 3, jj = i & 7;
        cst[i] = g_ct[b * HSZ + j0 + jj];
    }
    float* stg = reinterpret_cast<float*>(smem + SB_STG);
    __syncthreads();

    // warp tile: 16 warps = 8 m-groups (16 rows) x 2 n-groups (16 cols)
    const int mb = (wid & 7) * 16, nbW = (wid >> 3) * 16;
    const int bL = tid >> 2, qL = tid & 3;   // LSTM: thread -> (b, 2 hidden units)

    // prefetch xg for step 0 (2 units x 4 gates = 8 floats)
    float4 xv[2];
    {
        const float* xgp = g_xg + (size_t)bL * GSZ + n0 + qL * 8;
        xv[0] = __ldcg(reinterpret_cast<const float4*>(xgp));
        xv[1] = __ldcg(reinterpret_cast<const float4*>(xgp + 4));
    }

    for (int s = 0; s < Ss; s++) {
        issue_chunkA(sb, tid, 0, 0);

        float c[2][4] = {};
        for (int kc = 0; kc < 12; kc++) {
            CP_WAIT0();
            __syncthreads();
            if (kc < 11) issue_chunkA(sb, tid, kc + 1, (kc + 1) & 1);

            const uint32_t abuf = sb + SB_A + (uint32_t)(kc & 1) * 32768u;
#pragma unroll
            for (int ks2 = 0; ks2 < 4; ks2++) {
                uint32_t ah[4], al[4], bh[4], bl[4];
                int kbA = ks2 * 2 + (lane >> 4);
                int rowA = mb + (lane & 15);
                uint32_t offA = abuf + (uint32_t)rowA * 128 + (uint32_t)((kbA ^ (rowA & 7)) << 4);
                ldsm4(ah[0], ah[1], ah[2], ah[3], offA);
                ldsm4(al[0], al[1], al[2], al[3], offA + 16384u);
                int rowB = nbW + ((lane >> 4) << 3) + (lane & 7);
                int kbB = kc * 8 + ks2 * 2 + ((lane >> 3) & 1);
                uint32_t offB = (uint32_t)rowB * 1536 + (uint32_t)((kbB ^ (rowB & 7)) << 4);
                ldsm4(bh[0], bh[1], bh[2], bh[3], sb + SB_BHI + offB);
                ldsm4(bl[0], bl[1], bl[2], bl[3], sb + SB_BLO + offB);
                mma16816(c[0], ah, bh[0], bh[1]);
                mma16816(c[1], ah, bh[2], bh[3]);
                mma16816(c[0], al, bh[0], bh[1]);
                mma16816(c[1], al, bh[2], bh[3]);
                mma16816(c[0], ah, bl[0], bl[1]);
                mma16816(c[1], ah, bl[2], bl[3]);
            }
        }
        __syncthreads();

        // stage C tile (128b x 32n)
        {
            int r0 = mb + (lane >> 2);
            int col0 = nbW + (lane & 3) * 2;
#pragma unroll
            for (int nj = 0; nj < 2; nj++) {
                int col = col0 + nj * 8;
                stg[r0 * 36 + col]           = c[nj][0];
                stg[r0 * 36 + col + 1]       = c[nj][1];
                stg[(r0 + 8) * 36 + col]     = c[nj][2];
                stg[(r0 + 8) * 36 + col + 1] = c[nj][3];
            }
        }
        __syncthreads();

        // fused LSTM: 2 hidden units per thread
        float hq[2], cq[2];
        {
            const float* sp = stg + bL * 36 + qL * 8;
#pragma unroll
            for (int q = 0; q < 2; q++) {
                float vi = xv[q].x + sp[q * 4 + 0];
                float vf = xv[q].y + sp[q * 4 + 1];
                float vg = xv[q].z + sp[q * 4 + 2];
                float vo = xv[q].w + sp[q * 4 + 3];
                float ig = fsig(vi), fg = fsig(vf), gg = ftanh(vg), og = fsig(vo);
                int ci = bL * 8 + qL * 2 + q;
                float cc = fg * cst[ci] + ig * gg;
                cst[ci] = cc;
                hq[q] = og * ftanh(cc);
                cq[q] = cc;
            }
            float rem;
            ushort2 H, L;
            H.x = bf_hi(hq[0], rem); L.x = __bfloat16_as_ushort(__float2bfloat16(rem));
            H.y = bf_hi(hq[1], rem); L.y = __bfloat16_as_ushort(__float2bfloat16(rem));
            int hoff = bL * HSZ + j0 + qL * 2;
            *reinterpret_cast<ushort2*>(g_Hh + hoff) = H;
            *reinterpret_cast<ushort2*>(g_Hl + hoff) = L;
        }

        // split barrier: arrive, shadow work, wait
        __syncthreads();
        if (tid == 0) {
            __threadfence();
            if (atomicAdd(&g_cnt, 1u) == NCTAR - 1u) {
                g_cnt = 0;
                __threadfence();
                g_epoch = (unsigned)(s + 1);
            }
        }
        {
            int hoff = bL * HSZ + j0 + qL * 2;
            float2 hv = make_float2(hq[0], hq[1]);
            *reinterpret_cast<float2*>(out + ((size_t)bL * Ss + s) * HSZ + j0 + qL * 2) = hv;
            if (s == Ss - 1) {
                *reinterpret_cast<float2*>(out + HID + hoff) = hv;
                *reinterpret_cast<float2*>(out + HID + STATE + hoff) = make_float2(cq[0], cq[1]);
            }
            if (s + 1 < Ss) {
                const float* xgp = g_xg + ((size_t)(s + 1) * Bb + bL) * GSZ + n0 + qL * 8;
                xv[0] = __ldcg(reinterpret_cast<const float4*>(xgp));
                xv[1] = __ldcg(reinterpret_cast<const float4*>(xgp + 4));
            }
        }
        if (tid == 0) {
            while (g_epoch <= (unsigned)s) { }
        }
        __syncthreads();
    }
}

extern "C" void kernel_launch(void* const* d_in, const int* in_sizes, int n_in,
                              void* d_out, int out_size) {
    const float* x    = (const float*)d_in[0];
    const float* h0   = (const float*)d_in[1];
    const float* c0   = (const float*)d_in[2];
    const float* W    = (const float*)d_in[3];
    const float* U    = (const float*)d_in[4];
    const float* bias = (const float*)d_in[5];
    const float* G    = (const float*)d_in[6];
    float* out = (float*)d_out;
    (void)in_sizes; (void)n_in; (void)out_size;

    cudaFuncSetAttribute(xw_gemm, cudaFuncAttributeMaxDynamicSharedMemorySize, SMEMSZ);
    cudaFuncSetAttribute(recur2,  cudaFuncAttributeMaxDynamicSharedMemorySize, SMEM2);

    convAll<<<(Bb * Ss * ISZ + 255) / 256, 256>>>(x, h0, c0, W, U, bias, G);
    xw_gemm<<<dim3(24, 128), 256, SMEMSZ>>>();
    dummyK<<<1, 1>>>();
    recur2<<<NCTAR, RTHREADS, SMEM2>>>(out);
}

// round 11
// speedup vs baseline: 1.0482x; 1.0482x over previous
#include <cuda_runtime.h>
#include <cuda_bf16.h>
#include <cstdint>

#define Bb 128
#define Ss 128
#define ISZ 384
#define HSZ 768
#define GSZ 3072
#define HID (Bb*Ss*HSZ)
#define STATE (Bb*HSZ)
#define NCTAR 96
#define RTHREADS 512

// ---------------- device scratch ----------------
__device__ __nv_bfloat16 g_Umt_hi[GSZ*HSZ];
__device__ __nv_bfloat16 g_Umt_lo[GSZ*HSZ];
__device__ __nv_bfloat16 g_Wmt_hi[GSZ*ISZ];
__device__ __nv_bfloat16 g_Wmt_lo[GSZ*ISZ];
__device__ __nv_bfloat16 g_Xh[Bb*Ss*ISZ];
__device__ __nv_bfloat16 g_Xl[Bb*Ss*ISZ];
__device__ float g_xg[(size_t)Ss*Bb*GSZ];     // [s][b][n] includes bias
__device__ __nv_bfloat16 g_Hh[STATE];         // h bf16 hi [b][k]
__device__ __nv_bfloat16 g_Hl[STATE];         // h bf16 lo [b][k]
__device__ float g_ct[STATE];                 // c0 fp32 [b][j]
__device__ float g_biasp[GSZ];
__device__ unsigned g_cnt;
__device__ volatile unsigned g_epoch;

// ---------------- helpers ----------------
__device__ __forceinline__ uint32_t smem_u32(const void* p) {
    uint32_t a;
    asm("{ .reg .u64 t; cvta.to.shared.u64 t, %1; cvt.u32.u64 %0, t; }" : "=r"(a) : "l"(p));
    return a;
}
__device__ __forceinline__ void ldsm4(uint32_t& r0, uint32_t& r1, uint32_t& r2, uint32_t& r3, uint32_t addr) {
    asm volatile("ldmatrix.sync.aligned.m8n8.x4.shared.b16 {%0,%1,%2,%3}, [%4];"
                 : "=r"(r0), "=r"(r1), "=r"(r2), "=r"(r3) : "r"(addr));
}
__device__ __forceinline__ void mma16816(float* c, const uint32_t* a, uint32_t b0, uint32_t b1) {
    asm volatile("mma.sync.aligned.m16n8k16.row.col.f32.bf16.bf16.f32 "
                 "{%0,%1,%2,%3}, {%4,%5,%6,%7}, {%8,%9}, {%0,%1,%2,%3};"
                 : "+f"(c[0]), "+f"(c[1]), "+f"(c[2]), "+f"(c[3])
                 : "r"(a[0]), "r"(a[1]), "r"(a[2]), "r"(a[3]), "r"(b0), "r"(b1));
}
__device__ __forceinline__ unsigned short bf_hi(float x, float& rem) {
    __nv_bfloat16 h = __float2bfloat16(x);
    rem = x - __bfloat162float(h);
    return __bfloat16_as_ushort(h);
}
__device__ __forceinline__ float fsig(float x)  { return 1.0f / (1.0f + __expf(-x)); }
__device__ __forceinline__ float ftanh(float x) { return 2.0f / (1.0f + __expf(-2.0f * x)) - 1.0f; }

#define CP_ASYNC_CG(dst, src) asm volatile("cp.async.cg.shared.global [%0], [%1], 16;" :: "r"(dst), "l"(src))
#define CP_COMMIT()           asm volatile("cp.async.commit_group;" ::: "memory")
#define CP_WAIT0()            asm volatile("cp.async.wait_group 0;" ::: "memory")
#define CP_WAIT1()            asm volatile("cp.async.wait_group 1;" ::: "memory")

// ================= recur2 SMEM layout (3-stage A pipeline) =================
#define SB_BHI 0
#define SB_BLO 49152
#define SB_A   98304          /* 3 bufs x 32768 (hi 16K + lo 16K) */
#define SB_STG 196608         /* C stage: 128 x 36 floats = 18432 */
#define SB_CST 215040         /* c state: 128 x 8 floats = 4096 */
#define SMEM2  219136

// ================= xw_gemm SMEM geometry =================
#define ROWB 272
#define TILEB (128 * ROWB)
#define OFF_A_HI 0u
#define OFF_A_LO 34816u
#define OFF_B_HI 69632u
#define OFF_B_LO 104448u
#define SMEMSZ   139264

__device__ __forceinline__ void mma_tile3(uint32_t sA, uint32_t sB, int lane, int mb, int nb, float c[2][8][4]) {
    uint32_t aBase = sA + (uint32_t)(mb + (lane & 15)) * ROWB + (uint32_t)(lane >> 4) * 16;
    uint32_t bBase = sB + (uint32_t)(nb + ((lane >> 4) << 3) + (lane & 7)) * ROWB + (uint32_t)((lane >> 3) & 1) * 16;
#pragma unroll
    for (int k0 = 0; k0 < 128; k0 += 16) {
        uint32_t ah[2][4], al[2][4];
#pragma unroll
        for (int mi = 0; mi < 2; mi++) {
            uint32_t ao = aBase + (uint32_t)(mi * 16 * ROWB + k0 * 2);
            ldsm4(ah[mi][0], ah[mi][1], ah[mi][2], ah[mi][3], ao);
            ldsm4(al[mi][0], al[mi][1], al[mi][2], al[mi][3], ao + TILEB);
        }
#pragma unroll
        for (int nj = 0; nj < 4; nj++) {
            uint32_t bo = bBase + (uint32_t)(nj * 16 * ROWB + k0 * 2);
            uint32_t bh0, bh1, bh2, bh3, bl0, bl1, bl2, bl3;
            ldsm4(bh0, bh1, bh2, bh3, bo);
            ldsm4(bl0, bl1, bl2, bl3, bo + TILEB);
#pragma unroll
            for (int mi = 0; mi < 2; mi++) {
                mma16816(c[mi][nj * 2],     ah[mi], bh0, bh1);
                mma16816(c[mi][nj * 2 + 1], ah[mi], bh2, bh3);
                mma16816(c[mi][nj * 2],     al[mi], bh0, bh1);
                mma16816(c[mi][nj * 2 + 1], al[mi], bh2, bh3);
                mma16816(c[mi][nj * 2],     ah[mi], bl0, bl1);
                mma16816(c[mi][nj * 2 + 1], ah[mi], bl2, bl3);
            }
        }
    }
}

// ---------------- one-time conversions ----------------
__global__ void convAll(const float* __restrict__ x, const float* __restrict__ h0,
                        const float* __restrict__ c0, const float* __restrict__ W,
                        const float* __restrict__ U, const float* __restrict__ bias,
                        const float* __restrict__ G) {
    int idx = blockIdx.x * blockDim.x + threadIdx.x;
    float rem;
    if (idx == 0) { g_cnt = 0; g_epoch = 0; }
    if (idx < Bb * Ss * ISZ) {
        int f = idx % ISZ, r = idx / ISZ;
        int s = r >> 7, b = r & 127;
        float v = x[((size_t)b * Ss + s) * ISZ + f];
        g_Xh[idx] = __ushort_as_bfloat16(bf_hi(v, rem));
        g_Xl[idx] = __float2bfloat16(rem);
    }
    if (idx < GSZ * HSZ) {
        int n = idx / HSZ, k = idx % HSZ;
        int j = n >> 2, g = n & 3;
        float v = U[(size_t)k * GSZ + g * HSZ + j] * G[(k >> 5) * 24 + (j >> 5)];
        g_Umt_hi[idx] = __ushort_as_bfloat16(bf_hi(v, rem));
        g_Umt_lo[idx] = __float2bfloat16(rem);
    }
    if (idx < GSZ * ISZ) {
        int n = idx / ISZ, k = idx % ISZ;
        int j = n >> 2, g = n & 3;
        float v = W[(size_t)k * GSZ + g * HSZ + j] * G[(k >> 4) * 24 + (j >> 5)];
        g_Wmt_hi[idx] = __ushort_as_bfloat16(bf_hi(v, rem));
        g_Wmt_lo[idx] = __float2bfloat16(rem);
    }
    if (idx < STATE) {
        g_Hh[idx] = __ushort_as_bfloat16(bf_hi(h0[idx], rem));
        g_Hl[idx] = __float2bfloat16(rem);
        g_ct[idx] = c0[idx];
        if (idx < GSZ) g_biasp[idx] = bias[(idx & 3) * HSZ + (idx >> 2)];
    }
}

// keeps recur2 in the 4th-launch ncu capture slot
__global__ void dummyK() {}

// ---------------- input projection ----------------
__global__ void __launch_bounds__(256, 1) xw_gemm() {
    extern __shared__ char smem[];
    const uint32_t sb = smem_u32(smem);
    const int tid = threadIdx.x, wid = tid >> 5, lane = tid & 31;
    const int n0 = blockIdx.x * 128, s = blockIdx.y;

    float c[2][8][4];
#pragma unroll
    for (int i = 0; i < 2; i++)
#pragma unroll
        for (int j = 0; j < 8; j++)
#pragma unroll
            for (int q = 0; q < 4; q++) c[i][j][q] = 0.0f;

    for (int ck = 0; ck < 3; ck++) {
        if (ck) __syncthreads();
        for (int i = tid; i < 8192; i += 256) {
            int ab = i >> 12;
            int hl = (i >> 11) & 1, r = i & 2047, row = r >> 4, blk = r & 15;
            const __nv_bfloat16* src;
            uint32_t dst;
            if (ab == 0) {
                src = (hl ? g_Xl : g_Xh) + (size_t)(s * 128 + row) * ISZ + ck * 128 + blk * 8;
                dst = (hl ? OFF_A_LO : OFF_A_HI);
            } else {
                src = (hl ? g_Wmt_lo : g_Wmt_hi) + (size_t)(n0 + row) * ISZ + ck * 128 + blk * 8;
                dst = (hl ? OFF_B_LO : OFF_B_HI);
            }
            dst += (uint32_t)row * ROWB + (uint32_t)blk * 16;
            *reinterpret_cast<uint4*>(smem + dst) = *reinterpret_cast<const uint4*>(src);
        }
        __syncthreads();
        mma_tile3(sb + OFF_A_HI, sb + OFF_B_HI, lane, (wid & 3) * 32, (wid >> 2) * 64, c);
    }
    {
        const int nb = (wid >> 2) * 64;
        const int col0 = n0 + nb + (lane & 3) * 2;
#pragma unroll
        for (int ni = 0; ni < 8; ni++) {
            float b0 = g_biasp[col0 + ni * 8];
            float b1 = g_biasp[col0 + ni * 8 + 1];
#pragma unroll
            for (int mi = 0; mi < 2; mi++) {
                c[mi][ni][0] += b0; c[mi][ni][1] += b1;
                c[mi][ni][2] += b0; c[mi][ni][3] += b1;
            }
        }
    }
    __syncthreads();
    {
        float* CS = reinterpret_cast<float*>(smem);
        const int mb = (wid & 3) * 32, nb = (wid >> 2) * 64;
        const int r0 = mb + (lane >> 2);
        const int col0 = nb + (lane & 3) * 2;
#pragma unroll
        for (int mi = 0; mi < 2; mi++)
#pragma unroll
            for (int ni = 0; ni < 8; ni++) {
                float* p0 = &CS[(r0 + mi * 16) * 132 + col0 + ni * 8];
                p0[0] = c[mi][ni][0]; p0[1] = c[mi][ni][1];
                float* p1 = &CS[(r0 + mi * 16 + 8) * 132 + col0 + ni * 8];
                p1[0] = c[mi][ni][2]; p1[1] = c[mi][ni][3];
            }
        __syncthreads();
        const int b = tid >> 1, half = tid & 1;
        const float4* src = reinterpret_cast<const float4*>(&CS[b * 132 + half * 64]);
        float4* dst = reinterpret_cast<float4*>(g_xg + (size_t)s * Bb * GSZ + n0 + (size_t)b * GSZ + half * 64);
#pragma unroll
        for (int q = 0; q < 16; q++) dst[q] = src[q];
    }
}

// ---------------- persistent fused recurrence (512 thr, 3-stage pipeline) ----------------
__device__ __forceinline__ void issue_chunkA(uint32_t sb, int tid, int kc, int buf) {
#pragma unroll
    for (int q = 0; q < 4; q++) {
        int idx = tid + RTHREADS * q;
        int hl = idx >> 10, r = idx & 1023, b = r >> 3, kb = r & 7;
        const __nv_bfloat16* src = (hl ? g_Hl : g_Hh) + (size_t)b * HSZ + kc * 64 + kb * 8;
        uint32_t dst = sb + SB_A + (uint32_t)buf * 32768u + (uint32_t)hl * 16384u +
                       (uint32_t)b * 128u + (uint32_t)((kb ^ (b & 7)) << 4);
        CP_ASYNC_CG(dst, src);
    }
    CP_COMMIT();
}

__global__ void __launch_bounds__(RTHREADS, 1) recur2(float* __restrict__ out) {
    extern __shared__ char smem[];
    const uint32_t sb = smem_u32(smem);
    const int tid = threadIdx.x, wid = tid >> 5, lane = tid & 31;
    const int nt = blockIdx.x;
    const int n0 = nt * 32;
    const int j0 = nt * 8;

    // B resident (once)
    for (int i = tid; i < 6144; i += RTHREADS) {
        int hl = (i >= 3072);
        int r = hl ? (i - 3072) : i;
        int n = r / 96, kb = r % 96;
        const __nv_bfloat16* src = (hl ? g_Umt_lo : g_Umt_hi) + (size_t)(n0 + n) * HSZ + kb * 8;
        uint32_t dst = (hl ? SB_BLO : SB_BHI) + (uint32_t)n * 1536 + (uint32_t)((kb ^ (n & 7)) << 4);
        *reinterpret_cast<uint4*>(smem + dst) = *reinterpret_cast<const uint4*>(src);
    }
    float* cst = reinterpret_cast<float*>(smem + SB_CST);
    for (int i = tid; i < 1024; i += RTHREADS) {
        int b = i >> 3, jj = i & 7;
        cst[i] = g_ct[b * HSZ + j0 + jj];
    }
    float* stg = reinterpret_cast<float*>(smem + SB_STG);
    __syncthreads();

    // warp tile: 16 warps = 8 m-groups (16 rows) x 2 n-groups (16 cols)
    const int mb = (wid & 7) * 16, nbW = (wid >> 3) * 16;
    const int bL = tid >> 2, qL = tid & 3;

    // prefetch xg for step 0
    float4 xv[2];
    {
        const float* xgp = g_xg + (size_t)bL * GSZ + n0 + qL * 8;
        xv[0] = __ldcg(reinterpret_cast<const float4*>(xgp));
        xv[1] = __ldcg(reinterpret_cast<const float4*>(xgp + 4));
    }

    for (int s = 0; s < Ss; s++) {
        issue_chunkA(sb, tid, 0, 0);
        issue_chunkA(sb, tid, 1, 1);

        float c[2][4] = {};
        for (int kc = 0; kc < 12; kc++) {
            if (kc < 11) CP_WAIT1(); else CP_WAIT0();
            __syncthreads();               // chunk kc visible to all; all warps done with buf (kc-1)%3
            if (kc < 10) issue_chunkA(sb, tid, kc + 2, (kc + 2) % 3);

            const uint32_t abuf = sb + SB_A + (uint32_t)(kc % 3) * 32768u;
#pragma unroll
            for (int ks2 = 0; ks2 < 4; ks2++) {
                uint32_t ah[4], al[4], bh[4], bl[4];
                int kbA = ks2 * 2 + (lane >> 4);
                int rowA = mb + (lane & 15);
                uint32_t offA = abuf + (uint32_t)rowA * 128 + (uint32_t)((kbA ^ (rowA & 7)) << 4);
                ldsm4(ah[0], ah[1], ah[2], ah[3], offA);
                ldsm4(al[0], al[1], al[2], al[3], offA + 16384u);
                int rowB = nbW + ((lane >> 4) << 3) + (lane & 7);
                int kbB = kc * 8 + ks2 * 2 + ((lane >> 3) & 1);
                uint32_t offB = (uint32_t)rowB * 1536 + (uint32_t)((kbB ^ (rowB & 7)) << 4);
                ldsm4(bh[0], bh[1], bh[2], bh[3], sb + SB_BHI + offB);
                ldsm4(bl[0], bl[1], bl[2], bl[3], sb + SB_BLO + offB);
                mma16816(c[0], ah, bh[0], bh[1]);
                mma16816(c[1], ah, bh[2], bh[3]);
                mma16816(c[0], al, bh[0], bh[1]);
                mma16816(c[1], al, bh[2], bh[3]);
                mma16816(c[0], ah, bl[0], bl[1]);
                mma16816(c[1], ah, bl[2], bl[3]);
            }
        }

        // stage C tile (no barrier needed before: each warp writes from own regs)
        {
            int r0 = mb + (lane >> 2);
            int col0 = nbW + (lane & 3) * 2;
#pragma unroll
            for (int nj = 0; nj < 2; nj++) {
                int col = col0 + nj * 8;
                stg[r0 * 36 + col]           = c[nj][0];
                stg[r0 * 36 + col + 1]       = c[nj][1];
                stg[(r0 + 8) * 36 + col]     = c[nj][2];
                stg[(r0 + 8) * 36 + col + 1] = c[nj][3];
            }
        }
        __syncthreads();

        // fused LSTM: 2 hidden units per thread
        float hq[2], cq[2];
        {
            const float* sp = stg + bL * 36 + qL * 8;
#pragma unroll
            for (int q = 0; q < 2; q++) {
                float vi = xv[q].x + sp[q * 4 + 0];
                float vf = xv[q].y + sp[q * 4 + 1];
                float vg = xv[q].z + sp[q * 4 + 2];
                float vo = xv[q].w + sp[q * 4 + 3];
                float ig = fsig(vi), fg = fsig(vf), gg = ftanh(vg), og = fsig(vo);
                int ci = bL * 8 + qL * 2 + q;
                float cc = fg * cst[ci] + ig * gg;
                cst[ci] = cc;
                hq[q] = og * ftanh(cc);
                cq[q] = cc;
            }
            float rem;
            ushort2 H, L;
            H.x = bf_hi(hq[0], rem); L.x = __bfloat16_as_ushort(__float2bfloat16(rem));
            H.y = bf_hi(hq[1], rem); L.y = __bfloat16_as_ushort(__float2bfloat16(rem));
            int hoff = bL * HSZ + j0 + qL * 2;
            *reinterpret_cast<ushort2*>(g_Hh + hoff) = H;
            *reinterpret_cast<ushort2*>(g_Hl + hoff) = L;
        }

        // split barrier: arrive, shadow work, wait
        __syncthreads();
        if (tid == 0) {
            __threadfence();
            if (atomicAdd(&g_cnt, 1u) == NCTAR - 1u) {
                g_cnt = 0;
                __threadfence();
                g_epoch = (unsigned)(s + 1);
            }
        }
        {
            int hoff = bL * HSZ + j0 + qL * 2;
            float2 hv = make_float2(hq[0], hq[1]);
            *reinterpret_cast<float2*>(out + ((size_t)bL * Ss + s) * HSZ + j0 + qL * 2) = hv;
            if (s == Ss - 1) {
                *reinterpret_cast<float2*>(out + HID + hoff) = hv;
                *reinterpret_cast<float2*>(out + HID + STATE + hoff) = make_float2(cq[0], cq[1]);
            }
            if (s + 1 < Ss) {
                const float* xgp = g_xg + ((size_t)(s + 1) * Bb + bL) * GSZ + n0 + qL * 8;
                xv[0] = __ldcg(reinterpret_cast<const float4*>(xgp));
                xv[1] = __ldcg(reinterpret_cast<const float4*>(xgp + 4));
            }
        }
        if (tid == 0) {
            while (g_epoch <= (unsigned)s) { }
        }
        __syncthreads();
    }
}

extern "C" void kernel_launch(void* const* d_in, const int* in_sizes, int n_in,
                              void* d_out, int out_size) {
    const float* x    = (const float*)d_in[0];
    const float* h0   = (const float*)d_in[1];
    const float* c0   = (const float*)d_in[2];
    const float* W    = (const float*)d_in[3];
    const float* U    = (const float*)d_in[4];
    const float* bias = (const float*)d_in[5];
    const float* G    = (const float*)d_in[6];
    float* out = (float*)d_out;
    (void)in_sizes; (void)n_in; (void)out_size;

    cudaFuncSetAttribute(xw_gemm, cudaFuncAttributeMaxDynamicSharedMemorySize, SMEMSZ);
    cudaFuncSetAttribute(recur2,  cudaFuncAttributeMaxDynamicSharedMemorySize, SMEM2);

    convAll<<<(Bb * Ss * ISZ + 255) / 256, 256>>>(x, h0, c0, W, U, bias, G);
    xw_gemm<<<dim3(24, 128), 256, SMEMSZ>>>();
    dummyK<<<1, 1>>>();
    recur2<<<NCTAR, RTHREADS, SMEM2>>>(out);
}

// round 12
// speedup vs baseline: 1.0589x; 1.0102x over previous
#include <cuda_runtime.h>
#include <cuda_bf16.h>
#include <cstdint>

#define Bb 128
#define Ss 128
#define ISZ 384
#define HSZ 768
#define GSZ 3072
#define HID (Bb*Ss*HSZ)
#define STATE (Bb*HSZ)
#define NCTAR 96
#define RTHREADS 512

// ---------------- device scratch ----------------
__device__ __nv_bfloat16 g_Umt_hi[GSZ*HSZ];
__device__ __nv_bfloat16 g_Umt_lo[GSZ*HSZ];
__device__ __nv_bfloat16 g_Wmt_hi[GSZ*ISZ];
__device__ __nv_bfloat16 g_Wmt_lo[GSZ*ISZ];
__device__ __nv_bfloat16 g_Xh[Bb*Ss*ISZ];
__device__ __nv_bfloat16 g_Xl[Bb*Ss*ISZ];
__device__ float g_xg[(size_t)Ss*Bb*GSZ];     // [s][b][n] includes bias
__device__ __nv_bfloat16 g_Hh[STATE];         // h bf16 hi [b][k]
__device__ __nv_bfloat16 g_Hl[STATE];         // h bf16 lo [b][k]
__device__ float g_ct[STATE];                 // c0 fp32 [b][j]
__device__ float g_biasp[GSZ];
__device__ unsigned g_cnt;
__device__ volatile unsigned g_epoch;

// ---------------- helpers ----------------
__device__ __forceinline__ uint32_t smem_u32(const void* p) {
    uint32_t a;
    asm("{ .reg .u64 t; cvta.to.shared.u64 t, %1; cvt.u32.u64 %0, t; }" : "=r"(a) : "l"(p));
    return a;
}
__device__ __forceinline__ void ldsm4(uint32_t& r0, uint32_t& r1, uint32_t& r2, uint32_t& r3, uint32_t addr) {
    asm volatile("ldmatrix.sync.aligned.m8n8.x4.shared.b16 {%0,%1,%2,%3}, [%4];"
                 : "=r"(r0), "=r"(r1), "=r"(r2), "=r"(r3) : "r"(addr));
}
__device__ __forceinline__ void mma16816(float* c, const uint32_t* a, uint32_t b0, uint32_t b1) {
    asm volatile("mma.sync.aligned.m16n8k16.row.col.f32.bf16.bf16.f32 "
                 "{%0,%1,%2,%3}, {%4,%5,%6,%7}, {%8,%9}, {%0,%1,%2,%3};"
                 : "+f"(c[0]), "+f"(c[1]), "+f"(c[2]), "+f"(c[3])
                 : "r"(a[0]), "r"(a[1]), "r"(a[2]), "r"(a[3]), "r"(b0), "r"(b1));
}
__device__ __forceinline__ unsigned short bf_hi(float x, float& rem) {
    __nv_bfloat16 h = __float2bfloat16(x);
    rem = x - __bfloat162float(h);
    return __bfloat16_as_ushort(h);
}
__device__ __forceinline__ float fsig(float x)  { return 1.0f / (1.0f + __expf(-x)); }
__device__ __forceinline__ float ftanh(float x) { return 2.0f / (1.0f + __expf(-2.0f * x)) - 1.0f; }

#define CP_ASYNC_CG(dst, src) asm volatile("cp.async.cg.shared.global [%0], [%1], 16;" :: "r"(dst), "l"(src))
#define CP_COMMIT()           asm volatile("cp.async.commit_group;" ::: "memory")
#define CP_WAIT0()            asm volatile("cp.async.wait_group 0;" ::: "memory")
#define CP_WAIT1()            asm volatile("cp.async.wait_group 1;" ::: "memory")
#define BAR_PAIR(id)          asm volatile("bar.sync %0, 64;" :: "r"(id) : "memory")

// ================= recur2 SMEM layout (3-stage A pipeline) =================
#define SB_BHI 0
#define SB_BLO 49152
#define SB_A   98304          /* 3 bufs x 32768 (hi 16K + lo 16K) */
#define SB_STG 196608         /* C stage: 128 x 36 floats = 18432 */
#define SB_CST 215040         /* c state: 128 x 8 floats = 4096 */
#define SMEM2  219136

// ================= xw_gemm SMEM geometry =================
#define ROWB 272
#define TILEB (128 * ROWB)
#define OFF_A_HI 0u
#define OFF_A_LO 34816u
#define OFF_B_HI 69632u
#define OFF_B_LO 104448u
#define SMEMSZ   139264

__device__ __forceinline__ void mma_tile3(uint32_t sA, uint32_t sB, int lane, int mb, int nb, float c[2][8][4]) {
    uint32_t aBase = sA + (uint32_t)(mb + (lane & 15)) * ROWB + (uint32_t)(lane >> 4) * 16;
    uint32_t bBase = sB + (uint32_t)(nb + ((lane >> 4) << 3) + (lane & 7)) * ROWB + (uint32_t)((lane >> 3) & 1) * 16;
#pragma unroll
    for (int k0 = 0; k0 < 128; k0 += 16) {
        uint32_t ah[2][4], al[2][4];
#pragma unroll
        for (int mi = 0; mi < 2; mi++) {
            uint32_t ao = aBase + (uint32_t)(mi * 16 * ROWB + k0 * 2);
            ldsm4(ah[mi][0], ah[mi][1], ah[mi][2], ah[mi][3], ao);
            ldsm4(al[mi][0], al[mi][1], al[mi][2], al[mi][3], ao + TILEB);
        }
#pragma unroll
        for (int nj = 0; nj < 4; nj++) {
            uint32_t bo = bBase + (uint32_t)(nj * 16 * ROWB + k0 * 2);
            uint32_t bh0, bh1, bh2, bh3, bl0, bl1, bl2, bl3;
            ldsm4(bh0, bh1, bh2, bh3, bo);
            ldsm4(bl0, bl1, bl2, bl3, bo + TILEB);
#pragma unroll
            for (int mi = 0; mi < 2; mi++) {
                mma16816(c[mi][nj * 2],     ah[mi], bh0, bh1);
                mma16816(c[mi][nj * 2 + 1], ah[mi], bh2, bh3);
                mma16816(c[mi][nj * 2],     al[mi], bh0, bh1);
                mma16816(c[mi][nj * 2 + 1], al[mi], bh2, bh3);
                mma16816(c[mi][nj * 2],     ah[mi], bl0, bl1);
                mma16816(c[mi][nj * 2 + 1], ah[mi], bl2, bl3);
            }
        }
    }
}

// ---------------- one-time conversions ----------------
__global__ void convAll(const float* __restrict__ x, const float* __restrict__ h0,
                        const float* __restrict__ c0, const float* __restrict__ W,
                        const float* __restrict__ U, const float* __restrict__ bias,
                        const float* __restrict__ G) {
    int idx = blockIdx.x * blockDim.x + threadIdx.x;
    float rem;
    if (idx == 0) { g_cnt = 0; g_epoch = 0; }
    if (idx < Bb * Ss * ISZ) {
        int f = idx % ISZ, r = idx / ISZ;
        int s = r >> 7, b = r & 127;
        float v = x[((size_t)b * Ss + s) * ISZ + f];
        g_Xh[idx] = __ushort_as_bfloat16(bf_hi(v, rem));
        g_Xl[idx] = __float2bfloat16(rem);
    }
    if (idx < GSZ * HSZ) {
        int n = idx / HSZ, k = idx % HSZ;
        int j = n >> 2, g = n & 3;
        float v = U[(size_t)k * GSZ + g * HSZ + j] * G[(k >> 5) * 24 + (j >> 5)];
        g_Umt_hi[idx] = __ushort_as_bfloat16(bf_hi(v, rem));
        g_Umt_lo[idx] = __float2bfloat16(rem);
    }
    if (idx < GSZ * ISZ) {
        int n = idx / ISZ, k = idx % ISZ;
        int j = n >> 2, g = n & 3;
        float v = W[(size_t)k * GSZ + g * HSZ + j] * G[(k >> 4) * 24 + (j >> 5)];
        g_Wmt_hi[idx] = __ushort_as_bfloat16(bf_hi(v, rem));
        g_Wmt_lo[idx] = __float2bfloat16(rem);
    }
    if (idx < STATE) {
        g_Hh[idx] = __ushort_as_bfloat16(bf_hi(h0[idx], rem));
        g_Hl[idx] = __float2bfloat16(rem);
        g_ct[idx] = c0[idx];
        if (idx < GSZ) g_biasp[idx] = bias[(idx & 3) * HSZ + (idx >> 2)];
    }
}

// keeps recur2 in the 4th-launch ncu capture slot
__global__ void dummyK() {}

// ---------------- input projection ----------------
__global__ void __launch_bounds__(256, 1) xw_gemm() {
    extern __shared__ char smem[];
    const uint32_t sb = smem_u32(smem);
    const int tid = threadIdx.x, wid = tid >> 5, lane = tid & 31;
    const int n0 = blockIdx.x * 128, s = blockIdx.y;

    float c[2][8][4];
#pragma unroll
    for (int i = 0; i < 2; i++)
#pragma unroll
        for (int j = 0; j < 8; j++)
#pragma unroll
            for (int q = 0; q < 4; q++) c[i][j][q] = 0.0f;

    for (int ck = 0; ck < 3; ck++) {
        if (ck) __syncthreads();
        for (int i = tid; i < 8192; i += 256) {
            int ab = i >> 12;
            int hl = (i >> 11) & 1, r = i & 2047, row = r >> 4, blk = r & 15;
            const __nv_bfloat16* src;
            uint32_t dst;
            if (ab == 0) {
                src = (hl ? g_Xl : g_Xh) + (size_t)(s * 128 + row) * ISZ + ck * 128 + blk * 8;
                dst = (hl ? OFF_A_LO : OFF_A_HI);
            } else {
                src = (hl ? g_Wmt_lo : g_Wmt_hi) + (size_t)(n0 + row) * ISZ + ck * 128 + blk * 8;
                dst = (hl ? OFF_B_LO : OFF_B_HI);
            }
            dst += (uint32_t)row * ROWB + (uint32_t)blk * 16;
            *reinterpret_cast<uint4*>(smem + dst) = *reinterpret_cast<const uint4*>(src);
        }
        __syncthreads();
        mma_tile3(sb + OFF_A_HI, sb + OFF_B_HI, lane, (wid & 3) * 32, (wid >> 2) * 64, c);
    }
    {
        const int nb = (wid >> 2) * 64;
        const int col0 = n0 + nb + (lane & 3) * 2;
#pragma unroll
        for (int ni = 0; ni < 8; ni++) {
            float b0 = g_biasp[col0 + ni * 8];
            float b1 = g_biasp[col0 + ni * 8 + 1];
#pragma unroll
            for (int mi = 0; mi < 2; mi++) {
                c[mi][ni][0] += b0; c[mi][ni][1] += b1;
                c[mi][ni][2] += b0; c[mi][ni][3] += b1;
            }
        }
    }
    __syncthreads();
    {
        float* CS = reinterpret_cast<float*>(smem);
        const int mb = (wid & 3) * 32, nb = (wid >> 2) * 64;
        const int r0 = mb + (lane >> 2);
        const int col0 = nb + (lane & 3) * 2;
#pragma unroll
        for (int mi = 0; mi < 2; mi++)
#pragma unroll
            for (int ni = 0; ni < 8; ni++) {
                float* p0 = &CS[(r0 + mi * 16) * 132 + col0 + ni * 8];
                p0[0] = c[mi][ni][0]; p0[1] = c[mi][ni][1];
                float* p1 = &CS[(r0 + mi * 16 + 8) * 132 + col0 + ni * 8];
                p1[0] = c[mi][ni][2]; p1[1] = c[mi][ni][3];
            }
        __syncthreads();
        const int b = tid >> 1, half = tid & 1;
        const float4* src = reinterpret_cast<const float4*>(&CS[b * 132 + half * 64]);
        float4* dst = reinterpret_cast<float4*>(g_xg + (size_t)s * Bb * GSZ + n0 + (size_t)b * GSZ + half * 64);
#pragma unroll
        for (int q = 0; q < 16; q++) dst[q] = src[q];
    }
}

// ---------------- persistent fused recurrence (pair-synced k-loop) ----------------
// pair = 2 warps sharing m-group; each pair copies its own 16 batch rows per chunk.
__device__ __forceinline__ void issue_pairA(uint32_t sb, int mgrp, int pairLane, int kc, int buf) {
#pragma unroll
    for (int q = 0; q < 4; q++) {
        int idx = pairLane + 64 * q;              // 0..255
        int hl = idx >> 7, r = idx & 127, row16 = r >> 3, kb = r & 7;
        int b = mgrp * 16 + row16;
        const __nv_bfloat16* src = (hl ? g_Hl : g_Hh) + (size_t)b * HSZ + kc * 64 + kb * 8;
        uint32_t dst = sb + SB_A + (uint32_t)buf * 32768u + (uint32_t)hl * 16384u +
                       (uint32_t)b * 128u + (uint32_t)((kb ^ (b & 7)) << 4);
        CP_ASYNC_CG(dst, src);
    }
    CP_COMMIT();
}

__global__ void __launch_bounds__(RTHREADS, 1) recur2(float* __restrict__ out) {
    extern __shared__ char smem[];
    const uint32_t sb = smem_u32(smem);
    const int tid = threadIdx.x, wid = tid >> 5, lane = tid & 31;
    const int nt = blockIdx.x;
    const int n0 = nt * 32;
    const int j0 = nt * 8;

    // B resident (once)
    for (int i = tid; i < 6144; i += RTHREADS) {
        int hl = (i >= 3072);
        int r = hl ? (i - 3072) : i;
        int n = r / 96, kb = r % 96;
        const __nv_bfloat16* src = (hl ? g_Umt_lo : g_Umt_hi) + (size_t)(n0 + n) * HSZ + kb * 8;
        uint32_t dst = (hl ? SB_BLO : SB_BHI) + (uint32_t)n * 1536 + (uint32_t)((kb ^ (n & 7)) << 4);
        *reinterpret_cast<uint4*>(smem + dst) = *reinterpret_cast<const uint4*>(src);
    }
    float* cst = reinterpret_cast<float*>(smem + SB_CST);
    for (int i = tid; i < 1024; i += RTHREADS) {
        int b = i >> 3, jj = i & 7;
        cst[i] = g_ct[b * HSZ + j0 + jj];
    }
    float* stg = reinterpret_cast<float*>(smem + SB_STG);
    __syncthreads();

    // 16 warps = 8 m-groups x 2 n-groups; pair = same m-group
    const int mgrp = wid & 7, ngrp = wid >> 3;
    const int mb = mgrp * 16, nbW = ngrp * 16;
    const int pairLane = ngrp * 32 + lane;        // 0..63 within pair
    const int barId = 1 + mgrp;                    // named barrier per pair
    const int bL = tid >> 2, qL = tid & 3;

    // prefetch xg for step 0
    float4 xv[2];
    {
        const float* xgp = g_xg + (size_t)bL * GSZ + n0 + qL * 8;
        xv[0] = __ldcg(reinterpret_cast<const float4*>(xgp));
        xv[1] = __ldcg(reinterpret_cast<const float4*>(xgp + 4));
    }

    for (int s = 0; s < Ss; s++) {
        issue_pairA(sb, mgrp, pairLane, 0, 0);
        issue_pairA(sb, mgrp, pairLane, 1, 1);

        float c[2][4] = {};
        for (int kc = 0; kc < 12; kc++) {
            if (kc < 11) CP_WAIT1(); else CP_WAIT0();
            BAR_PAIR(barId);                       // pair's chunk kc visible to both warps
            if (kc < 10) issue_pairA(sb, mgrp, pairLane, kc + 2, (kc + 2) % 3);

            const uint32_t abuf = sb + SB_A + (uint32_t)(kc % 3) * 32768u;
#pragma unroll
            for (int ks2 = 0; ks2 < 4; ks2++) {
                uint32_t ah[4], al[4], bh[4], bl[4];
                int kbA = ks2 * 2 + (lane >> 4);
                int rowA = mb + (lane & 15);
                uint32_t offA = abuf + (uint32_t)rowA * 128 + (uint32_t)((kbA ^ (rowA & 7)) << 4);
                ldsm4(ah[0], ah[1], ah[2], ah[3], offA);
                ldsm4(al[0], al[1], al[2], al[3], offA + 16384u);
                int rowB = nbW + ((lane >> 4) << 3) + (lane & 7);
                int kbB = kc * 8 + ks2 * 2 + ((lane >> 3) & 1);
                uint32_t offB = (uint32_t)rowB * 1536 + (uint32_t)((kbB ^ (rowB & 7)) << 4);
                ldsm4(bh[0], bh[1], bh[2], bh[3], sb + SB_BHI + offB);
                ldsm4(bl[0], bl[1], bl[2], bl[3], sb + SB_BLO + offB);
                mma16816(c[0], ah, bh[0], bh[1]);
                mma16816(c[1], ah, bh[2], bh[3]);
                mma16816(c[0], al, bh[0], bh[1]);
                mma16816(c[1], al, bh[2], bh[3]);
                mma16816(c[0], ah, bl[0], bl[1]);
                mma16816(c[1], ah, bl[2], bl[3]);
            }
        }

        // stage C tile (per-warp own regs; pairs may be skewed — stg region is warp-disjoint)
        {
            int r0 = mb + (lane >> 2);
            int col0 = nbW + (lane & 3) * 2;
#pragma unroll
            for (int nj = 0; nj < 2; nj++) {
                int col = col0 + nj * 8;
                stg[r0 * 36 + col]           = c[nj][0];
                stg[r0 * 36 + col + 1]       = c[nj][1];
                stg[(r0 + 8) * 36 + col]     = c[nj][2];
                stg[(r0 + 8) * 36 + col + 1] = c[nj][3];
            }
        }
        __syncthreads();

        // fused LSTM: 2 hidden units per thread
        float hq[2], cq[2];
        {
            const float* sp = stg + bL * 36 + qL * 8;
#pragma unroll
            for (int q = 0; q < 2; q++) {
                float vi = xv[q].x + sp[q * 4 + 0];
                float vf = xv[q].y + sp[q * 4 + 1];
                float vg = xv[q].z + sp[q * 4 + 2];
                float vo = xv[q].w + sp[q * 4 + 3];
                float ig = fsig(vi), fg = fsig(vf), gg = ftanh(vg), og = fsig(vo);
                int ci = bL * 8 + qL * 2 + q;
                float cc = fg * cst[ci] + ig * gg;
                cst[ci] = cc;
                hq[q] = og * ftanh(cc);
                cq[q] = cc;
            }
            float rem;
            ushort2 H, L;
            H.x = bf_hi(hq[0], rem); L.x = __bfloat16_as_ushort(__float2bfloat16(rem));
            H.y = bf_hi(hq[1], rem); L.y = __bfloat16_as_ushort(__float2bfloat16(rem));
            int hoff = bL * HSZ + j0 + qL * 2;
            *reinterpret_cast<ushort2*>(g_Hh + hoff) = H;
            *reinterpret_cast<ushort2*>(g_Hl + hoff) = L;
        }

        // split grid barrier: arrive, shadow work, wait
        __syncthreads();
        if (tid == 0) {
            __threadfence();
            if (atomicAdd(&g_cnt, 1u) == NCTAR - 1u) {
                g_cnt = 0;
                __threadfence();
                g_epoch = (unsigned)(s + 1);
            }
        }
        {
            int hoff = bL * HSZ + j0 + qL * 2;
            float2 hv = make_float2(hq[0], hq[1]);
            *reinterpret_cast<float2*>(out + ((size_t)bL * Ss + s) * HSZ + j0 + qL * 2) = hv;
            if (s == Ss - 1) {
                *reinterpret_cast<float2*>(out + HID + hoff) = hv;
                *reinterpret_cast<float2*>(out + HID + STATE + hoff) = make_float2(cq[0], cq[1]);
            }
            if (s + 1 < Ss) {
                const float* xgp = g_xg + ((size_t)(s + 1) * Bb + bL) * GSZ + n0 + qL * 8;
                xv[0] = __ldcg(reinterpret_cast<const float4*>(xgp));
                xv[1] = __ldcg(reinterpret_cast<const float4*>(xgp + 4));
            }
        }
        if (tid == 0) {
            while (g_epoch <= (unsigned)s) { }
        }
        __syncthreads();
    }
}

extern "C" void kernel_launch(void* const* d_in, const int* in_sizes, int n_in,
                              void* d_out, int out_size) {
    const float* x    = (const float*)d_in[0];
    const float* h0   = (const float*)d_in[1];
    const float* c0   = (const float*)d_in[2];
    const float* W    = (const float*)d_in[3];
    const float* U    = (const float*)d_in[4];
    const float* bias = (const float*)d_in[5];
    const float* G    = (const float*)d_in[6];
    float* out = (float*)d_out;
    (void)in_sizes; (void)n_in; (void)out_size;

    cudaFuncSetAttribute(xw_gemm, cudaFuncAttributeMaxDynamicSharedMemorySize, SMEMSZ);
    cudaFuncSetAttribute(recur2,  cudaFuncAttributeMaxDynamicSharedMemorySize, SMEM2);

    convAll<<<(Bb * Ss * ISZ + 255) / 256, 256>>>(x, h0, c0, W, U, bias, G);
    xw_gemm<<<dim3(24, 128), 256, SMEMSZ>>>();
    dummyK<<<1, 1>>>();
    recur2<<<NCTAR, RTHREADS, SMEM2>>>(out);
}

// round 13
// speedup vs baseline: 1.2093x; 1.1420x over previous
#include <cuda_runtime.h>
#include <cuda_bf16.h>
#include <cuda_fp16.h>
#include <cstdint>

#define Bb 128
#define Ss 128
#define ISZ 384
#define HSZ 768
#define GSZ 3072
#define HID (Bb*Ss*HSZ)
#define STATE (Bb*HSZ)
#define NCTAR 96
#define RTHREADS 512

// ---------------- device scratch ----------------
__device__ __half g_Uf_hi[GSZ*HSZ];           // Um^T permuted fp16 hi [n][k]
__device__ __half g_Uf_lo[GSZ*HSZ];           // Um^T lo residual x 4096 (fp16)
__device__ __nv_bfloat16 g_Wmt_hi[GSZ*ISZ];   // W path stays bf16x3
__device__ __nv_bfloat16 g_Wmt_lo[GSZ*ISZ];
__device__ __nv_bfloat16 g_Xh[Bb*Ss*ISZ];
__device__ __nv_bfloat16 g_Xl[Bb*Ss*ISZ];
__device__ float g_xg[(size_t)Ss*Bb*GSZ];     // [s][b][n] includes bias
__device__ __half g_Hf[STATE];                // h fp16 [b][k]
__device__ float g_ct[STATE];                 // c fp32 [b][j]
__device__ float g_biasp[GSZ];
__device__ unsigned g_cnt;
__device__ volatile unsigned g_epoch;

// ---------------- helpers ----------------
__device__ __forceinline__ uint32_t smem_u32(const void* p) {
    uint32_t a;
    asm("{ .reg .u64 t; cvta.to.shared.u64 t, %1; cvt.u32.u64 %0, t; }" : "=r"(a) : "l"(p));
    return a;
}
__device__ __forceinline__ void ldsm4(uint32_t& r0, uint32_t& r1, uint32_t& r2, uint32_t& r3, uint32_t addr) {
    asm volatile("ldmatrix.sync.aligned.m8n8.x4.shared.b16 {%0,%1,%2,%3}, [%4];"
                 : "=r"(r0), "=r"(r1), "=r"(r2), "=r"(r3) : "r"(addr));
}
// bf16 mma (xw path)
__device__ __forceinline__ void mma16816(float* c, const uint32_t* a, uint32_t b0, uint32_t b1) {
    asm volatile("mma.sync.aligned.m16n8k16.row.col.f32.bf16.bf16.f32 "
                 "{%0,%1,%2,%3}, {%4,%5,%6,%7}, {%8,%9}, {%0,%1,%2,%3};"
                 : "+f"(c[0]), "+f"(c[1]), "+f"(c[2]), "+f"(c[3])
                 : "r"(a[0]), "r"(a[1]), "r"(a[2]), "r"(a[3]), "r"(b0), "r"(b1));
}
// fp16 mma (recurrence path)
__device__ __forceinline__ void mma16816h(float* c, const uint32_t* a, uint32_t b0, uint32_t b1) {
    asm volatile("mma.sync.aligned.m16n8k16.row.col.f32.f16.f16.f32 "
                 "{%0,%1,%2,%3}, {%4,%5,%6,%7}, {%8,%9}, {%0,%1,%2,%3};"
                 : "+f"(c[0]), "+f"(c[1]), "+f"(c[2]), "+f"(c[3])
                 : "r"(a[0]), "r"(a[1]), "r"(a[2]), "r"(a[3]), "r"(b0), "r"(b1));
}
__device__ __forceinline__ unsigned short bf_hi(float x, float& rem) {
    __nv_bfloat16 h = __float2bfloat16(x);
    rem = x - __bfloat162float(h);
    return __bfloat16_as_ushort(h);
}
__device__ __forceinline__ float fsig(float x)  { return 1.0f / (1.0f + __expf(-x)); }
__device__ __forceinline__ float ftanh(float x) { return 2.0f / (1.0f + __expf(-2.0f * x)) - 1.0f; }

#define CP_ASYNC_CG(dst, src) asm volatile("cp.async.cg.shared.global [%0], [%1], 16;" :: "r"(dst), "l"(src))
#define CP_COMMIT()           asm volatile("cp.async.commit_group;" ::: "memory")
#define CP_WAIT0()            asm volatile("cp.async.wait_group 0;" ::: "memory")
#define CP_WAIT1()            asm volatile("cp.async.wait_group 1;" ::: "memory")
#define BAR_PAIR(id)          asm volatile("bar.sync %0, 64;" :: "r"(id) : "memory")

// ================= recur2 SMEM layout (fp16, 3-stage single-A pipeline) =================
#define SB_BHI 0              /* Um hi: 32 x 768 fp16 = 49152 */
#define SB_BLO 49152          /* Um lo(x4096): 49152 */
#define SB_A   98304          /* 3 bufs x 16384 (A fp16 chunk 128x64) */
#define SB_STG 147456         /* C stage: 128 x 36 floats = 18432 */
#define SB_CST 165888         /* c state: 128 x 8 floats = 4096 */
#define SMEM2  169984

// ================= xw_gemm SMEM geometry (unchanged) =================
#define ROWB 272
#define TILEB (128 * ROWB)
#define OFF_A_HI 0u
#define OFF_A_LO 34816u
#define OFF_B_HI 69632u
#define OFF_B_LO 104448u
#define SMEMSZ   139264

__device__ __forceinline__ void mma_tile3(uint32_t sA, uint32_t sB, int lane, int mb, int nb, float c[2][8][4]) {
    uint32_t aBase = sA + (uint32_t)(mb + (lane & 15)) * ROWB + (uint32_t)(lane >> 4) * 16;
    uint32_t bBase = sB + (uint32_t)(nb + ((lane >> 4) << 3) + (lane & 7)) * ROWB + (uint32_t)((lane >> 3) & 1) * 16;
#pragma unroll
    for (int k0 = 0; k0 < 128; k0 += 16) {
        uint32_t ah[2][4], al[2][4];
#pragma unroll
        for (int mi = 0; mi < 2; mi++) {
            uint32_t ao = aBase + (uint32_t)(mi * 16 * ROWB + k0 * 2);
            ldsm4(ah[mi][0], ah[mi][1], ah[mi][2], ah[mi][3], ao);
            ldsm4(al[mi][0], al[mi][1], al[mi][2], al[mi][3], ao + TILEB);
        }
#pragma unroll
        for (int nj = 0; nj < 4; nj++) {
            uint32_t bo = bBase + (uint32_t)(nj * 16 * ROWB + k0 * 2);
            uint32_t bh0, bh1, bh2, bh3, bl0, bl1, bl2, bl3;
            ldsm4(bh0, bh1, bh2, bh3, bo);
            ldsm4(bl0, bl1, bl2, bl3, bo + TILEB);
#pragma unroll
            for (int mi = 0; mi < 2; mi++) {
                mma16816(c[mi][nj * 2],     ah[mi], bh0, bh1);
                mma16816(c[mi][nj * 2 + 1], ah[mi], bh2, bh3);
                mma16816(c[mi][nj * 2],     al[mi], bh0, bh1);
                mma16816(c[mi][nj * 2 + 1], al[mi], bh2, bh3);
                mma16816(c[mi][nj * 2],     ah[mi], bl0, bl1);
                mma16816(c[mi][nj * 2 + 1], ah[mi], bl2, bl3);
            }
        }
    }
}

// ---------------- one-time conversions ----------------
__global__ void convAll(const float* __restrict__ x, const float* __restrict__ h0,
                        const float* __restrict__ c0, const float* __restrict__ W,
                        const float* __restrict__ U, const float* __restrict__ bias,
                        const float* __restrict__ G) {
    int idx = blockIdx.x * blockDim.x + threadIdx.x;
    float rem;
    if (idx == 0) { g_cnt = 0; g_epoch = 0; }
    if (idx < Bb * Ss * ISZ) {
        int f = idx % ISZ, r = idx / ISZ;
        int s = r >> 7, b = r & 127;
        float v = x[((size_t)b * Ss + s) * ISZ + f];
        g_Xh[idx] = __ushort_as_bfloat16(bf_hi(v, rem));
        g_Xl[idx] = __float2bfloat16(rem);
    }
    if (idx < GSZ * HSZ) {
        int n = idx / HSZ, k = idx % HSZ;
        int j = n >> 2, g = n & 3;
        float v = U[(size_t)k * GSZ + g * HSZ + j] * G[(k >> 5) * 24 + (j >> 5)];
        __half hv = __float2half_rn(v);
        g_Uf_hi[idx] = hv;
        g_Uf_lo[idx] = __float2half_rn((v - __half2float(hv)) * 4096.0f);
    }
    if (idx < GSZ * ISZ) {
        int n = idx / ISZ, k = idx % ISZ;
        int j = n >> 2, g = n & 3;
        float v = W[(size_t)k * GSZ + g * HSZ + j] * G[(k >> 4) * 24 + (j >> 5)];
        g_Wmt_hi[idx] = __ushort_as_bfloat16(bf_hi(v, rem));
        g_Wmt_lo[idx] = __float2bfloat16(rem);
    }
    if (idx < STATE) {
        g_Hf[idx] = __float2half_rn(h0[idx]);
        g_ct[idx] = c0[idx];
        if (idx < GSZ) g_biasp[idx] = bias[(idx & 3) * HSZ + (idx >> 2)];
    }
}

// keeps recur2 in the 4th-launch ncu capture slot
__global__ void dummyK() {}

// ---------------- input projection (unchanged bf16x3) ----------------
__global__ void __launch_bounds__(256, 1) xw_gemm() {
    extern __shared__ char smem[];
    const uint32_t sb = smem_u32(smem);
    const int tid = threadIdx.x, wid = tid >> 5, lane = tid & 31;
    const int n0 = blockIdx.x * 128, s = blockIdx.y;

    float c[2][8][4];
#pragma unroll
    for (int i = 0; i < 2; i++)
#pragma unroll
        for (int j = 0; j < 8; j++)
#pragma unroll
            for (int q = 0; q < 4; q++) c[i][j][q] = 0.0f;

    for (int ck = 0; ck < 3; ck++) {
        if (ck) __syncthreads();
        for (int i = tid; i < 8192; i += 256) {
            int ab = i >> 12;
            int hl = (i >> 11) & 1, r = i & 2047, row = r >> 4, blk = r & 15;
            const __nv_bfloat16* src;
            uint32_t dst;
            if (ab == 0) {
                src = (hl ? g_Xl : g_Xh) + (size_t)(s * 128 + row) * ISZ + ck * 128 + blk * 8;
                dst = (hl ? OFF_A_LO : OFF_A_HI);
            } else {
                src = (hl ? g_Wmt_lo : g_Wmt_hi) + (size_t)(n0 + row) * ISZ + ck * 128 + blk * 8;
                dst = (hl ? OFF_B_LO : OFF_B_HI);
            }
            dst += (uint32_t)row * ROWB + (uint32_t)blk * 16;
            *reinterpret_cast<uint4*>(smem + dst) = *reinterpret_cast<const uint4*>(src);
        }
        __syncthreads();
        mma_tile3(sb + OFF_A_HI, sb + OFF_B_HI, lane, (wid & 3) * 32, (wid >> 2) * 64, c);
    }
    {
        const int nb = (wid >> 2) * 64;
        const int col0 = n0 + nb + (lane & 3) * 2;
#pragma unroll
        for (int ni = 0; ni < 8; ni++) {
            float b0 = g_biasp[col0 + ni * 8];
            float b1 = g_biasp[col0 + ni * 8 + 1];
#pragma unroll
            for (int mi = 0; mi < 2; mi++) {
                c[mi][ni][0] += b0; c[mi][ni][1] += b1;
                c[mi][ni][2] += b0; c[mi][ni][3] += b1;
            }
        }
    }
    __syncthreads();
    {
        float* CS = reinterpret_cast<float*>(smem);
        const int mb = (wid & 3) * 32, nb = (wid >> 2) * 64;
        const int r0 = mb + (lane >> 2);
        const int col0 = nb + (lane & 3) * 2;
#pragma unroll
        for (int mi = 0; mi < 2; mi++)
#pragma unroll
            for (int ni = 0; ni < 8; ni++) {
                float* p0 = &CS[(r0 + mi * 16) * 132 + col0 + ni * 8];
                p0[0] = c[mi][ni][0]; p0[1] = c[mi][ni][1];
                float* p1 = &CS[(r0 + mi * 16 + 8) * 132 + col0 + ni * 8];
                p1[0] = c[mi][ni][2]; p1[1] = c[mi][ni][3];
            }
        __syncthreads();
        const int b = tid >> 1, half = tid & 1;
        const float4* src = reinterpret_cast<const float4*>(&CS[b * 132 + half * 64]);
        float4* dst = reinterpret_cast<float4*>(g_xg + (size_t)s * Bb * GSZ + n0 + (size_t)b * GSZ + half * 64);
#pragma unroll
        for (int q = 0; q < 16; q++) dst[q] = src[q];
    }
}

// ---------------- persistent fused recurrence (fp16, pair-synced) ----------------
// pair copies its 16 batch rows of the fp16 A chunk (2KB per pair per chunk)
__device__ __forceinline__ void issue_pairA(uint32_t sb, int mgrp, int pairLane, int kc, int buf) {
#pragma unroll
    for (int q = 0; q < 2; q++) {
        int idx = pairLane + 64 * q;              // 0..127
        int row16 = idx >> 3, kb = idx & 7;
        int b = mgrp * 16 + row16;
        const __half* src = g_Hf + (size_t)b * HSZ + kc * 64 + kb * 8;
        uint32_t dst = sb + SB_A + (uint32_t)buf * 16384u +
                       (uint32_t)b * 128u + (uint32_t)((kb ^ (b & 7)) << 4);
        CP_ASYNC_CG(dst, src);
    }
    CP_COMMIT();
}

__global__ void __launch_bounds__(RTHREADS, 1) recur2(float* __restrict__ out) {
    extern __shared__ char smem[];
    const uint32_t sb = smem_u32(smem);
    const int tid = threadIdx.x, wid = tid >> 5, lane = tid & 31;
    const int nt = blockIdx.x;
    const int n0 = nt * 32;
    const int j0 = nt * 8;

    // B resident (fp16 hi + scaled lo), once
    for (int i = tid; i < 6144; i += RTHREADS) {
        int hl = (i >= 3072);
        int r = hl ? (i - 3072) : i;
        int n = r / 96, kb = r % 96;
        const __half* src = (hl ? g_Uf_lo : g_Uf_hi) + (size_t)(n0 + n) * HSZ + kb * 8;
        uint32_t dst = (hl ? SB_BLO : SB_BHI) + (uint32_t)n * 1536 + (uint32_t)((kb ^ (n & 7)) << 4);
        *reinterpret_cast<uint4*>(smem + dst) = *reinterpret_cast<const uint4*>(src);
    }
    float* cst = reinterpret_cast<float*>(smem + SB_CST);
    for (int i = tid; i < 1024; i += RTHREADS) {
        int b = i >> 3, jj = i & 7;
        cst[i] = g_ct[b * HSZ + j0 + jj];
    }
    float* stg = reinterpret_cast<float*>(smem + SB_STG);
    __syncthreads();

    // 16 warps = 8 m-groups x 2 n-groups; pair = same m-group
    const int mgrp = wid & 7, ngrp = wid >> 3;
    const int mb = mgrp * 16, nbW = ngrp * 16;
    const int pairLane = ngrp * 32 + lane;
    const int barId = 1 + mgrp;
    const int bL = tid >> 2, qL = tid & 3;

    // prefetch xg for step 0
    float4 xv[2];
    {
        const float* xgp = g_xg + (size_t)bL * GSZ + n0 + qL * 8;
        xv[0] = __ldcg(reinterpret_cast<const float4*>(xgp));
        xv[1] = __ldcg(reinterpret_cast<const float4*>(xgp + 4));
    }

    for (int s = 0; s < Ss; s++) {
        issue_pairA(sb, mgrp, pairLane, 0, 0);
        issue_pairA(sb, mgrp, pairLane, 1, 1);

        float chi[2][4] = {}, clo[2][4] = {};
        for (int kc = 0; kc < 12; kc++) {
            if (kc < 11) CP_WAIT1(); else CP_WAIT0();
            BAR_PAIR(barId);
            if (kc < 10) issue_pairA(sb, mgrp, pairLane, kc + 2, (kc + 2) % 3);

            const uint32_t abuf = sb + SB_A + (uint32_t)(kc % 3) * 16384u;
#pragma unroll
            for (int ks2 = 0; ks2 < 4; ks2++) {
                uint32_t ah[4], bh[4], bl[4];
                int kbA = ks2 * 2 + (lane >> 4);
                int rowA = mb + (lane & 15);
                uint32_t offA = abuf + (uint32_t)rowA * 128 + (uint32_t)((kbA ^ (rowA & 7)) << 4);
                ldsm4(ah[0], ah[1], ah[2], ah[3], offA);
                int rowB = nbW + ((lane >> 4) << 3) + (lane & 7);
                int kbB = kc * 8 + ks2 * 2 + ((lane >> 3) & 1);
                uint32_t offB = (uint32_t)rowB * 1536 + (uint32_t)((kbB ^ (rowB & 7)) << 4);
                ldsm4(bh[0], bh[1], bh[2], bh[3], sb + SB_BHI + offB);
                ldsm4(bl[0], bl[1], bl[2], bl[3], sb + SB_BLO + offB);
                mma16816h(chi[0], ah, bh[0], bh[1]);
                mma16816h(chi[1], ah, bh[2], bh[3]);
                mma16816h(clo[0], ah, bl[0], bl[1]);
                mma16816h(clo[1], ah, bl[2], bl[3]);
            }
        }

        // stage C tile: c = chi + clo * 2^-12
        {
            int r0 = mb + (lane >> 2);
            int col0 = nbW + (lane & 3) * 2;
            const float kinv = 1.0f / 4096.0f;
#pragma unroll
            for (int nj = 0; nj < 2; nj++) {
                int col = col0 + nj * 8;
                stg[r0 * 36 + col]           = chi[nj][0] + clo[nj][0] * kinv;
                stg[r0 * 36 + col + 1]       = chi[nj][1] + clo[nj][1] * kinv;
                stg[(r0 + 8) * 36 + col]     = chi[nj][2] + clo[nj][2] * kinv;
                stg[(r0 + 8) * 36 + col + 1] = chi[nj][3] + clo[nj][3] * kinv;
            }
        }
        __syncthreads();

        // fused LSTM: 2 hidden units per thread
        float hq[2], cq[2];
        {
            const float* sp = stg + bL * 36 + qL * 8;
#pragma unroll
            for (int q = 0; q < 2; q++) {
                float vi = xv[q].x + sp[q * 4 + 0];
                float vf = xv[q].y + sp[q * 4 + 1];
                float vg = xv[q].z + sp[q * 4 + 2];
                float vo = xv[q].w + sp[q * 4 + 3];
                float ig = fsig(vi), fg = fsig(vf), gg = ftanh(vg), og = fsig(vo);
                int ci = bL * 8 + qL * 2 + q;
                float cc = fg * cst[ci] + ig * gg;
                cst[ci] = cc;
                hq[q] = og * ftanh(cc);
                cq[q] = cc;
            }
            __half2 hh;
            hh.x = __float2half_rn(hq[0]);
            hh.y = __float2half_rn(hq[1]);
            *reinterpret_cast<__half2*>(g_Hf + bL * HSZ + j0 + qL * 2) = hh;
        }

        // split grid barrier: arrive, shadow work, wait
        __syncthreads();
        if (tid == 0) {
            __threadfence();
            if (atomicAdd(&g_cnt, 1u) == NCTAR - 1u) {
                g_cnt = 0;
                __threadfence();
                g_epoch = (unsigned)(s + 1);
            }
        }
        {
            int hoff = bL * HSZ + j0 + qL * 2;
            float2 hv = make_float2(hq[0], hq[1]);
            *reinterpret_cast<float2*>(out + ((size_t)bL * Ss + s) * HSZ + j0 + qL * 2) = hv;
            if (s == Ss - 1) {
                *reinterpret_cast<float2*>(out + HID + hoff) = hv;
                *reinterpret_cast<float2*>(out + HID + STATE + hoff) = make_float2(cq[0], cq[1]);
            }
            if (s + 1 < Ss) {
                const float* xgp = g_xg + ((size_t)(s + 1) * Bb + bL) * GSZ + n0 + qL * 8;
                xv[0] = __ldcg(reinterpret_cast<const float4*>(xgp));
                xv[1] = __ldcg(reinterpret_cast<const float4*>(xgp + 4));
            }
        }
        if (tid == 0) {
            while (g_epoch <= (unsigned)s) { }
        }
        __syncthreads();
    }
}

extern "C" void kernel_launch(void* const* d_in, const int* in_sizes, int n_in,
                              void* d_out, int out_size) {
    const float* x    = (const float*)d_in[0];
    const float* h0   = (const float*)d_in[1];
    const float* c0   = (const float*)d_in[2];
    const float* W    = (const float*)d_in[3];
    const float* U    = (const float*)d_in[4];
    const float* bias = (const float*)d_in[5];
    const float* G    = (const float*)d_in[6];
    float* out = (float*)d_out;
    (void)in_sizes; (void)n_in; (void)out_size;

    cudaFuncSetAttribute(xw_gemm, cudaFuncAttributeMaxDynamicSharedMemorySize, SMEMSZ);
    cudaFuncSetAttribute(recur2,  cudaFuncAttributeMaxDynamicSharedMemorySize, SMEM2);

    convAll<<<(Bb * Ss * ISZ + 255) / 256, 256>>>(x, h0, c0, W, U, bias, G);
    xw_gemm<<<dim3(24, 128), 256, SMEMSZ>>>();
    dummyK<<<1, 1>>>();
    recur2<<<NCTAR, RTHREADS, SMEM2>>>(out);
}

// round 14
// speedup vs baseline: 1.3454x; 1.1126x over previous
#include <cuda_runtime.h>
#include <cuda_bf16.h>
#include <cuda_fp16.h>
#include <cstdint>

#define Bb 128
#define Ss 128
#define ISZ 384
#define HSZ 768
#define GSZ 3072
#define HID (Bb*Ss*HSZ)
#define STATE (Bb*HSZ)
#define NCTAR 96
#define RTHREADS 512

// ---------------- device scratch ----------------
__device__ __half g_Uf[GSZ*HSZ];              // Um^T permuted fp16 [n][k]
__device__ __nv_bfloat16 g_Wmt_hi[GSZ*ISZ];   // W path stays bf16x3
__device__ __nv_bfloat16 g_Wmt_lo[GSZ*ISZ];
__device__ __nv_bfloat16 g_Xh[Bb*Ss*ISZ];
__device__ __nv_bfloat16 g_Xl[Bb*Ss*ISZ];
__device__ float g_xg[(size_t)Ss*Bb*GSZ];     // [s][b][n] includes bias
__device__ __half g_Hf[STATE];                // h fp16 [b][k]
__device__ float g_ct[STATE];                 // c fp32 [b][j]
__device__ float g_biasp[GSZ];
__device__ unsigned g_cnt;
__device__ volatile unsigned g_epoch;

// ---------------- helpers ----------------
__device__ __forceinline__ uint32_t smem_u32(const void* p) {
    uint32_t a;
    asm("{ .reg .u64 t; cvta.to.shared.u64 t, %1; cvt.u32.u64 %0, t; }" : "=r"(a) : "l"(p));
    return a;
}
__device__ __forceinline__ void ldsm4(uint32_t& r0, uint32_t& r1, uint32_t& r2, uint32_t& r3, uint32_t addr) {
    asm volatile("ldmatrix.sync.aligned.m8n8.x4.shared.b16 {%0,%1,%2,%3}, [%4];"
                 : "=r"(r0), "=r"(r1), "=r"(r2), "=r"(r3) : "r"(addr));
}
// bf16 mma (xw path)
__device__ __forceinline__ void mma16816(float* c, const uint32_t* a, uint32_t b0, uint32_t b1) {
    asm volatile("mma.sync.aligned.m16n8k16.row.col.f32.bf16.bf16.f32 "
                 "{%0,%1,%2,%3}, {%4,%5,%6,%7}, {%8,%9}, {%0,%1,%2,%3};"
                 : "+f"(c[0]), "+f"(c[1]), "+f"(c[2]), "+f"(c[3])
                 : "r"(a[0]), "r"(a[1]), "r"(a[2]), "r"(a[3]), "r"(b0), "r"(b1));
}
// fp16 mma (recurrence path)
__device__ __forceinline__ void mma16816h(float* c, const uint32_t* a, uint32_t b0, uint32_t b1) {
    asm volatile("mma.sync.aligned.m16n8k16.row.col.f32.f16.f16.f32 "
                 "{%0,%1,%2,%3}, {%4,%5,%6,%7}, {%8,%9}, {%0,%1,%2,%3};"
                 : "+f"(c[0]), "+f"(c[1]), "+f"(c[2]), "+f"(c[3])
                 : "r"(a[0]), "r"(a[1]), "r"(a[2]), "r"(a[3]), "r"(b0), "r"(b1));
}
__device__ __forceinline__ unsigned short bf_hi(float x, float& rem) {
    __nv_bfloat16 h = __float2bfloat16(x);
    rem = x - __bfloat162float(h);
    return __bfloat16_as_ushort(h);
}
__device__ __forceinline__ float fsig(float x)  { return 1.0f / (1.0f + __expf(-x)); }
__device__ __forceinline__ float ftanh(float x) { return 2.0f / (1.0f + __expf(-2.0f * x)) - 1.0f; }

#define CP_ASYNC_CG(dst, src) asm volatile("cp.async.cg.shared.global [%0], [%1], 16;" :: "r"(dst), "l"(src))
#define CP_COMMIT()           asm volatile("cp.async.commit_group;" ::: "memory")
#define CP_WAIT0()            asm volatile("cp.async.wait_group 0;" ::: "memory")
#define CP_WAIT1()            asm volatile("cp.async.wait_group 1;" ::: "memory")
#define BAR_PAIR(id)          asm volatile("bar.sync %0, 64;" :: "r"(id) : "memory")

// ================= recur2 SMEM layout (fp16, single-B) =================
#define SB_BHI 0              /* Um: 32 x 768 fp16 = 49152 */
#define SB_A   49152          /* 3 bufs x 16384 (A fp16 chunk 128x64) */
#define SB_STG 98304          /* C stage: 128 x 36 floats = 18432 */
#define SB_CST 116736         /* c state: 128 x 8 floats = 4096 */
#define SMEM2  120832

// ================= xw_gemm SMEM geometry (unchanged) =================
#define ROWB 272
#define TILEB (128 * ROWB)
#define OFF_A_HI 0u
#define OFF_A_LO 34816u
#define OFF_B_HI 69632u
#define OFF_B_LO 104448u
#define SMEMSZ   139264

__device__ __forceinline__ void mma_tile3(uint32_t sA, uint32_t sB, int lane, int mb, int nb, float c[2][8][4]) {
    uint32_t aBase = sA + (uint32_t)(mb + (lane & 15)) * ROWB + (uint32_t)(lane >> 4) * 16;
    uint32_t bBase = sB + (uint32_t)(nb + ((lane >> 4) << 3) + (lane & 7)) * ROWB + (uint32_t)((lane >> 3) & 1) * 16;
#pragma unroll
    for (int k0 = 0; k0 < 128; k0 += 16) {
        uint32_t ah[2][4], al[2][4];
#pragma unroll
        for (int mi = 0; mi < 2; mi++) {
            uint32_t ao = aBase + (uint32_t)(mi * 16 * ROWB + k0 * 2);
            ldsm4(ah[mi][0], ah[mi][1], ah[mi][2], ah[mi][3], ao);
            ldsm4(al[mi][0], al[mi][1], al[mi][2], al[mi][3], ao + TILEB);
        }
#pragma unroll
        for (int nj = 0; nj < 4; nj++) {
            uint32_t bo = bBase + (uint32_t)(nj * 16 * ROWB + k0 * 2);
            uint32_t bh0, bh1, bh2, bh3, bl0, bl1, bl2, bl3;
            ldsm4(bh0, bh1, bh2, bh3, bo);
            ldsm4(bl0, bl1, bl2, bl3, bo + TILEB);
#pragma unroll
            for (int mi = 0; mi < 2; mi++) {
                mma16816(c[mi][nj * 2],     ah[mi], bh0, bh1);
                mma16816(c[mi][nj * 2 + 1], ah[mi], bh2, bh3);
                mma16816(c[mi][nj * 2],     al[mi], bh0, bh1);
                mma16816(c[mi][nj * 2 + 1], al[mi], bh2, bh3);
                mma16816(c[mi][nj * 2],     ah[mi], bl0, bl1);
                mma16816(c[mi][nj * 2 + 1], ah[mi], bl2, bl3);
            }
        }
    }
}

// ---------------- one-time conversions ----------------
__global__ void convAll(const float* __restrict__ x, const float* __restrict__ h0,
                        const float* __restrict__ c0, const float* __restrict__ W,
                        const float* __restrict__ U, const float* __restrict__ bias,
                        const float* __restrict__ G) {
    int idx = blockIdx.x * blockDim.x + threadIdx.x;
    float rem;
    if (idx == 0) { g_cnt = 0; g_epoch = 0; }
    if (idx < Bb * Ss * ISZ) {
        int f = idx % ISZ, r = idx / ISZ;
        int s = r >> 7, b = r & 127;
        float v = x[((size_t)b * Ss + s) * ISZ + f];
        g_Xh[idx] = __ushort_as_bfloat16(bf_hi(v, rem));
        g_Xl[idx] = __float2bfloat16(rem);
    }
    if (idx < GSZ * HSZ) {
        int n = idx / HSZ, k = idx % HSZ;
        int j = n >> 2, g = n & 3;
        float v = U[(size_t)k * GSZ + g * HSZ + j] * G[(k >> 5) * 24 + (j >> 5)];
        g_Uf[idx] = __float2half_rn(v);
    }
    if (idx < GSZ * ISZ) {
        int n = idx / ISZ, k = idx % ISZ;
        int j = n >> 2, g = n & 3;
        float v = W[(size_t)k * GSZ + g * HSZ + j] * G[(k >> 4) * 24 + (j >> 5)];
        g_Wmt_hi[idx] = __ushort_as_bfloat16(bf_hi(v, rem));
        g_Wmt_lo[idx] = __float2bfloat16(rem);
    }
    if (idx < STATE) {
        g_Hf[idx] = __float2half_rn(h0[idx]);
        g_ct[idx] = c0[idx];
        if (idx < GSZ) g_biasp[idx] = bias[(idx & 3) * HSZ + (idx >> 2)];
    }
}

// keeps recur2 in the 4th-launch ncu capture slot
__global__ void dummyK() {}

// ---------------- input projection (unchanged bf16x3) ----------------
__global__ void __launch_bounds__(256, 1) xw_gemm() {
    extern __shared__ char smem[];
    const uint32_t sb = smem_u32(smem);
    const int tid = threadIdx.x, wid = tid >> 5, lane = tid & 31;
    const int n0 = blockIdx.x * 128, s = blockIdx.y;

    float c[2][8][4];
#pragma unroll
    for (int i = 0; i < 2; i++)
#pragma unroll
        for (int j = 0; j < 8; j++)
#pragma unroll
            for (int q = 0; q < 4; q++) c[i][j][q] = 0.0f;

    for (int ck = 0; ck < 3; ck++) {
        if (ck) __syncthreads();
        for (int i = tid; i < 8192; i += 256) {
            int ab = i >> 12;
            int hl = (i >> 11) & 1, r = i & 2047, row = r >> 4, blk = r & 15;
            const __nv_bfloat16* src;
            uint32_t dst;
            if (ab == 0) {
                src = (hl ? g_Xl : g_Xh) + (size_t)(s * 128 + row) * ISZ + ck * 128 + blk * 8;
                dst = (hl ? OFF_A_LO : OFF_A_HI);
            } else {
                src = (hl ? g_Wmt_lo : g_Wmt_hi) + (size_t)(n0 + row) * ISZ + ck * 128 + blk * 8;
                dst = (hl ? OFF_B_LO : OFF_B_HI);
            }
            dst += (uint32_t)row * ROWB + (uint32_t)blk * 16;
            *reinterpret_cast<uint4*>(smem + dst) = *reinterpret_cast<const uint4*>(src);
        }
        __syncthreads();
        mma_tile3(sb + OFF_A_HI, sb + OFF_B_HI, lane, (wid & 3) * 32, (wid >> 2) * 64, c);
    }
    {
        const int nb = (wid >> 2) * 64;
        const int col0 = n0 + nb + (lane & 3) * 2;
#pragma unroll
        for (int ni = 0; ni < 8; ni++) {
            float b0 = g_biasp[col0 + ni * 8];
            float b1 = g_biasp[col0 + ni * 8 + 1];
#pragma unroll
            for (int mi = 0; mi < 2; mi++) {
                c[mi][ni][0] += b0; c[mi][ni][1] += b1;
                c[mi][ni][2] += b0; c[mi][ni][3] += b1;
            }
        }
    }
    __syncthreads();
    {
        float* CS = reinterpret_cast<float*>(smem);
        const int mb = (wid & 3) * 32, nb = (wid >> 2) * 64;
        const int r0 = mb + (lane >> 2);
        const int col0 = nb + (lane & 3) * 2;
#pragma unroll
        for (int mi = 0; mi < 2; mi++)
#pragma unroll
            for (int ni = 0; ni < 8; ni++) {
                float* p0 = &CS[(r0 + mi * 16) * 132 + col0 + ni * 8];
                p0[0] = c[mi][ni][0]; p0[1] = c[mi][ni][1];
                float* p1 = &CS[(r0 + mi * 16 + 8) * 132 + col0 + ni * 8];
                p1[0] = c[mi][ni][2]; p1[1] = c[mi][ni][3];
            }
        __syncthreads();
        const int b = tid >> 1, half = tid & 1;
        const float4* src = reinterpret_cast<const float4*>(&CS[b * 132 + half * 64]);
        float4* dst = reinterpret_cast<float4*>(g_xg + (size_t)s * Bb * GSZ + n0 + (size_t)b * GSZ + half * 64);
#pragma unroll
        for (int q = 0; q < 16; q++) dst[q] = src[q];
    }
}

// ---------------- persistent fused recurrence (fp16 single-B, pair-synced) ----------------
__device__ __forceinline__ void issue_pairA(uint32_t sb, int mgrp, int pairLane, int kc, int buf) {
#pragma unroll
    for (int q = 0; q < 2; q++) {
        int idx = pairLane + 64 * q;              // 0..127
        int row16 = idx >> 3, kb = idx & 7;
        int b = mgrp * 16 + row16;
        const __half* src = g_Hf + (size_t)b * HSZ + kc * 64 + kb * 8;
        uint32_t dst = sb + SB_A + (uint32_t)buf * 16384u +
                       (uint32_t)b * 128u + (uint32_t)((kb ^ (b & 7)) << 4);
        CP_ASYNC_CG(dst, src);
    }
    CP_COMMIT();
}

__global__ void __launch_bounds__(RTHREADS, 1) recur2(float* __restrict__ out) {
    extern __shared__ char smem[];
    const uint32_t sb = smem_u32(smem);
    const int tid = threadIdx.x, wid = tid >> 5, lane = tid & 31;
    const int nt = blockIdx.x;
    const int n0 = nt * 32;
    const int j0 = nt * 8;

    // B resident (fp16), once
    for (int i = tid; i < 3072; i += RTHREADS) {
        int n = i / 96, kb = i % 96;
        const __half* src = g_Uf + (size_t)(n0 + n) * HSZ + kb * 8;
        uint32_t dst = SB_BHI + (uint32_t)n * 1536 + (uint32_t)((kb ^ (n & 7)) << 4);
        *reinterpret_cast<uint4*>(smem + dst) = *reinterpret_cast<const uint4*>(src);
    }
    float* cst = reinterpret_cast<float*>(smem + SB_CST);
    for (int i = tid; i < 1024; i += RTHREADS) {
        int b = i >> 3, jj = i & 7;
        cst[i] = g_ct[b * HSZ + j0 + jj];
    }
    float* stg = reinterpret_cast<float*>(smem + SB_STG);
    __syncthreads();

    // 16 warps = 8 m-groups x 2 n-groups; pair = same m-group
    const int mgrp = wid & 7, ngrp = wid >> 3;
    const int mb = mgrp * 16, nbW = ngrp * 16;
    const int pairLane = ngrp * 32 + lane;
    const int barId = 1 + mgrp;
    const int bL = tid >> 2, qL = tid & 3;

    // prefetch xg for step 0
    float4 xv[2];
    {
        const float* xgp = g_xg + (size_t)bL * GSZ + n0 + qL * 8;
        xv[0] = __ldcg(reinterpret_cast<const float4*>(xgp));
        xv[1] = __ldcg(reinterpret_cast<const float4*>(xgp + 4));
    }

    for (int s = 0; s < Ss; s++) {
        issue_pairA(sb, mgrp, pairLane, 0, 0);
        issue_pairA(sb, mgrp, pairLane, 1, 1);

        float c[2][4] = {};
        for (int kc = 0; kc < 12; kc++) {
            if (kc < 11) CP_WAIT1(); else CP_WAIT0();
            BAR_PAIR(barId);
            if (kc < 10) issue_pairA(sb, mgrp, pairLane, kc + 2, (kc + 2) % 3);

            const uint32_t abuf = sb + SB_A + (uint32_t)(kc % 3) * 16384u;
#pragma unroll
            for (int ks2 = 0; ks2 < 4; ks2++) {
                uint32_t ah[4], bh[4];
                int kbA = ks2 * 2 + (lane >> 4);
                int rowA = mb + (lane & 15);
                uint32_t offA = abuf + (uint32_t)rowA * 128 + (uint32_t)((kbA ^ (rowA & 7)) << 4);
                ldsm4(ah[0], ah[1], ah[2], ah[3], offA);
                int rowB = nbW + ((lane >> 4) << 3) + (lane & 7);
                int kbB = kc * 8 + ks2 * 2 + ((lane >> 3) & 1);
                uint32_t offB = (uint32_t)rowB * 1536 + (uint32_t)((kbB ^ (rowB & 7)) << 4);
                ldsm4(bh[0], bh[1], bh[2], bh[3], SB_BHI + sb + offB);
                mma16816h(c[0], ah, bh[0], bh[1]);
                mma16816h(c[1], ah, bh[2], bh[3]);
            }
        }

        // stage C tile
        {
            int r0 = mb + (lane >> 2);
            int col0 = nbW + (lane & 3) * 2;
#pragma unroll
            for (int nj = 0; nj < 2; nj++) {
                int col = col0 + nj * 8;
                stg[r0 * 36 + col]           = c[nj][0];
                stg[r0 * 36 + col + 1]       = c[nj][1];
                stg[(r0 + 8) * 36 + col]     = c[nj][2];
                stg[(r0 + 8) * 36 + col + 1] = c[nj][3];
            }
        }
        __syncthreads();

        // fused LSTM: 2 hidden units per thread
        float hq[2], cq[2];
        {
            const float* sp = stg + bL * 36 + qL * 8;
#pragma unroll
            for (int q = 0; q < 2; q++) {
                float vi = xv[q].x + sp[q * 4 + 0];
                float vf = xv[q].y + sp[q * 4 + 1];
                float vg = xv[q].z + sp[q * 4 + 2];
                float vo = xv[q].w + sp[q * 4 + 3];
                float ig = fsig(vi), fg = fsig(vf), gg = ftanh(vg), og = fsig(vo);
                int ci = bL * 8 + qL * 2 + q;
                float cc = fg * cst[ci] + ig * gg;
                cst[ci] = cc;
                hq[q] = og * ftanh(cc);
                cq[q] = cc;
            }
            __half2 hh;
            hh.x = __float2half_rn(hq[0]);
            hh.y = __float2half_rn(hq[1]);
            *reinterpret_cast<__half2*>(g_Hf + bL * HSZ + j0 + qL * 2) = hh;
        }

        // split grid barrier: arrive, shadow work, wait
        __syncthreads();
        if (tid == 0) {
            __threadfence();
            if (atomicAdd(&g_cnt, 1u) == NCTAR - 1u) {
                g_cnt = 0;
                __threadfence();
                g_epoch = (unsigned)(s + 1);
            }
        }
        {
            int hoff = bL * HSZ + j0 + qL * 2;
            float2 hv = make_float2(hq[0], hq[1]);
            *reinterpret_cast<float2*>(out + ((size_t)bL * Ss + s) * HSZ + j0 + qL * 2) = hv;
            if (s == Ss - 1) {
                *reinterpret_cast<float2*>(out + HID + hoff) = hv;
                *reinterpret_cast<float2*>(out + HID + STATE + hoff) = make_float2(cq[0], cq[1]);
            }
            if (s + 1 < Ss) {
                const float* xgp = g_xg + ((size_t)(s + 1) * Bb + bL) * GSZ + n0 + qL * 8;
                xv[0] = __ldcg(reinterpret_cast<const float4*>(xgp));
                xv[1] = __ldcg(reinterpret_cast<const float4*>(xgp + 4));
            }
        }
        if (tid == 0) {
            while (g_epoch <= (unsigned)s) { }
        }
        __syncthreads();
    }
}

extern "C" void kernel_launch(void* const* d_in, const int* in_sizes, int n_in,
                              void* d_out, int out_size) {
    const float* x    = (const float*)d_in[0];
    const float* h0   = (const float*)d_in[1];
    const float* c0   = (const float*)d_in[2];
    const float* W    = (const float*)d_in[3];
    const float* U    = (const float*)d_in[4];
    const float* bias = (const float*)d_in[5];
    const float* G    = (const float*)d_in[6];
    float* out = (float*)d_out;
    (void)in_sizes; (void)n_in; (void)out_size;

    cudaFuncSetAttribute(xw_gemm, cudaFuncAttributeMaxDynamicSharedMemorySize, SMEMSZ);
    cudaFuncSetAttribute(recur2,  cudaFuncAttributeMaxDynamicSharedMemorySize, SMEM2);

    convAll<<<(Bb * Ss * ISZ + 255) / 256, 256>>>(x, h0, c0, W, U, bias, G);
    xw_gemm<<<dim3(24, 128), 256, SMEMSZ>>>();
    dummyK<<<1, 1>>>();
    recur2<<<NCTAR, RTHREADS, SMEM2>>>(out);
}

// round 15
// speedup vs baseline: 2.0452x; 1.5202x over previous
#include <cuda_runtime.h>
#include <cuda_bf16.h>
#include <cuda_fp16.h>
#include <cstdint>

#define Bb 128
#define Ss 128
#define ISZ 384
#define HSZ 768
#define GSZ 3072
#define HID (Bb*Ss*HSZ)
#define STATE (Bb*HSZ)
#define NCTAR 96
#define RTHREADS 512

// ---------------- device scratch ----------------
__device__ __half g_Uf[GSZ*HSZ];              // Um^T permuted fp16 [n][k]
__device__ __half g_Wf[GSZ*ISZ];              // Wm^T permuted fp16 [n][k]
__device__ __half g_Xf[Bb*Ss*ISZ];            // x fp16 [(s*128+b)][k]
__device__ float g_xg[(size_t)Ss*Bb*GSZ];     // [s][b][n] includes bias
__device__ __half g_Hf[STATE];                // h fp16 [b][k]
__device__ float g_ct[STATE];                 // c fp32 [b][j]
__device__ float g_biasp[GSZ];
__device__ unsigned g_cnt;
__device__ volatile unsigned g_epoch;

// ---------------- helpers ----------------
__device__ __forceinline__ uint32_t smem_u32(const void* p) {
    uint32_t a;
    asm("{ .reg .u64 t; cvta.to.shared.u64 t, %1; cvt.u32.u64 %0, t; }" : "=r"(a) : "l"(p));
    return a;
}
__device__ __forceinline__ void ldsm4(uint32_t& r0, uint32_t& r1, uint32_t& r2, uint32_t& r3, uint32_t addr) {
    asm volatile("ldmatrix.sync.aligned.m8n8.x4.shared.b16 {%0,%1,%2,%3}, [%4];"
                 : "=r"(r0), "=r"(r1), "=r"(r2), "=r"(r3) : "r"(addr));
}
__device__ __forceinline__ void mma16816h(float* c, const uint32_t* a, uint32_t b0, uint32_t b1) {
    asm volatile("mma.sync.aligned.m16n8k16.row.col.f32.f16.f16.f32 "
                 "{%0,%1,%2,%3}, {%4,%5,%6,%7}, {%8,%9}, {%0,%1,%2,%3};"
                 : "+f"(c[0]), "+f"(c[1]), "+f"(c[2]), "+f"(c[3])
                 : "r"(a[0]), "r"(a[1]), "r"(a[2]), "r"(a[3]), "r"(b0), "r"(b1));
}
__device__ __forceinline__ float fsig(float x)  { return 1.0f / (1.0f + __expf(-x)); }
__device__ __forceinline__ float ftanh(float x) { return 2.0f / (1.0f + __expf(-2.0f * x)) - 1.0f; }

#define CP_ASYNC_CG(dst, src) asm volatile("cp.async.cg.shared.global [%0], [%1], 16;" :: "r"(dst), "l"(src))
#define CP_COMMIT()           asm volatile("cp.async.commit_group;" ::: "memory")
#define CP_WAIT0()            asm volatile("cp.async.wait_group 0;" ::: "memory")
#define CP_WAIT1()            asm volatile("cp.async.wait_group 1;" ::: "memory")
#define BAR_PAIR(id)          asm volatile("bar.sync %0, 64;" :: "r"(id) : "memory")

// ================= recur2 SMEM layout (fp16, single-B) =================
#define SB_BHI 0              /* Um: 32 x 768 fp16 = 49152 */
#define SB_A   49152          /* 3 bufs x 16384 (A fp16 chunk 128x64) */
#define SB_STG 98304          /* C stage: 128 x 36 floats = 18432 */
#define SB_CST 116736         /* c state: 128 x 8 floats = 4096 */
#define SMEM2  120832

// ================= xw_gemm SMEM (fp16): A 32KB + B 32KB; C stage overlays =================
#define XW_A 0u
#define XW_B 32768u
#define SMEMX 69632           /* >= 128*132*4 for C staging */

// ---------------- one-time conversions ----------------
__global__ void convAll(const float* __restrict__ x, const float* __restrict__ h0,
                        const float* __restrict__ c0, const float* __restrict__ W,
                        const float* __restrict__ U, const float* __restrict__ bias,
                        const float* __restrict__ G) {
    int idx = blockIdx.x * blockDim.x + threadIdx.x;
    if (idx == 0) { g_cnt = 0; g_epoch = 0; }
    if (idx < Bb * Ss * ISZ) {
        int f = idx % ISZ, r = idx / ISZ;
        int s = r >> 7, b = r & 127;
        g_Xf[idx] = __float2half_rn(x[((size_t)b * Ss + s) * ISZ + f]);
    }
    if (idx < GSZ * HSZ) {
        int n = idx / HSZ, k = idx % HSZ;
        int j = n >> 2, g = n & 3;
        float v = U[(size_t)k * GSZ + g * HSZ + j] * G[(k >> 5) * 24 + (j >> 5)];
        g_Uf[idx] = __float2half_rn(v);
    }
    if (idx < GSZ * ISZ) {
        int n = idx / ISZ, k = idx % ISZ;
        int j = n >> 2, g = n & 3;
        float v = W[(size_t)k * GSZ + g * HSZ + j] * G[(k >> 4) * 24 + (j >> 5)];
        g_Wf[idx] = __float2half_rn(v);
    }
    if (idx < STATE) {
        g_Hf[idx] = __float2half_rn(h0[idx]);
        g_ct[idx] = c0[idx];
        if (idx < GSZ) g_biasp[idx] = bias[(idx & 3) * HSZ + (idx >> 2)];
    }
}

// keeps recur2 in the 4th-launch ncu capture slot
__global__ void dummyK() {}

// ---------------- input projection (fp16 single-term) ----------------
// 256B rows (128 fp16), XOR swizzle on 16B blocks within 8-row groups.
__global__ void __launch_bounds__(256, 1) xw_gemm() {
    extern __shared__ char smem[];
    const uint32_t sb = smem_u32(smem);
    const int tid = threadIdx.x, wid = tid >> 5, lane = tid & 31;
    const int n0 = blockIdx.x * 128, s = blockIdx.y;
    const int mb = (wid & 3) * 32, nb = (wid >> 2) * 64;

    float c[2][8][4];
#pragma unroll
    for (int i = 0; i < 2; i++)
#pragma unroll
        for (int j = 0; j < 8; j++)
#pragma unroll
            for (int q = 0; q < 4; q++) c[i][j][q] = 0.0f;

    for (int ck = 0; ck < 3; ck++) {
        if (ck) __syncthreads();
        // load A (X) and B (Wf) chunk tiles: 128 rows x 128 fp16 each
        for (int i = tid; i < 4096; i += 256) {
            int ab = i >> 11;                // 0=A, 1=B
            int r = i & 2047, row = r >> 4, kb = r & 15;
            const __half* src = ab
                ? g_Wf + (size_t)(n0 + row) * ISZ + ck * 128 + kb * 8
                : g_Xf + (size_t)(s * 128 + row) * ISZ + ck * 128 + kb * 8;
            uint32_t dst = (ab ? XW_B : XW_A) + (uint32_t)row * 256 + (uint32_t)((kb ^ (row & 7)) << 4);
            *reinterpret_cast<uint4*>(smem + dst) = *reinterpret_cast<const uint4*>(src);
        }
        __syncthreads();
#pragma unroll
        for (int k0 = 0; k0 < 8; k0++) {
            uint32_t a[2][4], b[4][4];
#pragma unroll
            for (int mi = 0; mi < 2; mi++) {
                int rowA = mb + mi * 16 + (lane & 15);
                int kbA = k0 * 2 + (lane >> 4);
                ldsm4(a[mi][0], a[mi][1], a[mi][2], a[mi][3],
                      sb + XW_A + (uint32_t)rowA * 256 + (uint32_t)((kbA ^ (rowA & 7)) << 4));
            }
#pragma unroll
            for (int nj = 0; nj < 4; nj++) {
                int rowB = nb + nj * 16 + ((lane >> 4) << 3) + (lane & 7);
                int kbB = k0 * 2 + ((lane >> 3) & 1);
                ldsm4(b[nj][0], b[nj][1], b[nj][2], b[nj][3],
                      sb + XW_B + (uint32_t)rowB * 256 + (uint32_t)((kbB ^ (rowB & 7)) << 4));
#pragma unroll
                for (int mi = 0; mi < 2; mi++) {
                    mma16816h(c[mi][nj * 2],     a[mi], b[nj][0], b[nj][1]);
                    mma16816h(c[mi][nj * 2 + 1], a[mi], b[nj][2], b[nj][3]);
                }
            }
        }
    }
    // fold permuted bias
    {
        const int col0 = n0 + nb + (lane & 3) * 2;
#pragma unroll
        for (int ni = 0; ni < 8; ni++) {
            float b0 = g_biasp[col0 + ni * 8];
            float b1 = g_biasp[col0 + ni * 8 + 1];
#pragma unroll
            for (int mi = 0; mi < 2; mi++) {
                c[mi][ni][0] += b0; c[mi][ni][1] += b1;
                c[mi][ni][2] += b0; c[mi][ni][3] += b1;
            }
        }
    }
    __syncthreads();
    // stage + coalesced store
    {
        float* CS = reinterpret_cast<float*>(smem);
        const int r0 = mb + (lane >> 2);
        const int col0 = nb + (lane & 3) * 2;
#pragma unroll
        for (int mi = 0; mi < 2; mi++)
#pragma unroll
            for (int ni = 0; ni < 8; ni++) {
                float* p0 = &CS[(r0 + mi * 16) * 132 + col0 + ni * 8];
                p0[0] = c[mi][ni][0]; p0[1] = c[mi][ni][1];
                float* p1 = &CS[(r0 + mi * 16 + 8) * 132 + col0 + ni * 8];
                p1[0] = c[mi][ni][2]; p1[1] = c[mi][ni][3];
            }
        __syncthreads();
        const int b = tid >> 1, half = tid & 1;
        const float4* src = reinterpret_cast<const float4*>(&CS[b * 132 + half * 64]);
        float4* dst = reinterpret_cast<float4*>(g_xg + (size_t)s * Bb * GSZ + n0 + (size_t)b * GSZ + half * 64);
#pragma unroll
        for (int q = 0; q < 16; q++) dst[q] = src[q];
    }
}

// ---------------- persistent fused recurrence (fp16 single-B, pair-synced) ----------------
__device__ __forceinline__ void issue_pairA(uint32_t sb, int mgrp, int pairLane, int kc, int buf) {
#pragma unroll
    for (int q = 0; q < 2; q++) {
        int idx = pairLane + 64 * q;              // 0..127
        int row16 = idx >> 3, kb = idx & 7;
        int b = mgrp * 16 + row16;
        const __half* src = g_Hf + (size_t)b * HSZ + kc * 64 + kb * 8;
        uint32_t dst = sb + SB_A + (uint32_t)buf * 16384u +
                       (uint32_t)b * 128u + (uint32_t)((kb ^ (b & 7)) << 4);
        CP_ASYNC_CG(dst, src);
    }
    CP_COMMIT();
}

__global__ void __launch_bounds__(RTHREADS, 1) recur2(float* __restrict__ out) {
    extern __shared__ char smem[];
    const uint32_t sb = smem_u32(smem);
    const int tid = threadIdx.x, wid = tid >> 5, lane = tid & 31;
    const int nt = blockIdx.x;
    const int n0 = nt * 32;
    const int j0 = nt * 8;

    // B resident (fp16), once
    for (int i = tid; i < 3072; i += RTHREADS) {
        int n = i / 96, kb = i % 96;
        const __half* src = g_Uf + (size_t)(n0 + n) * HSZ + kb * 8;
        uint32_t dst = SB_BHI + (uint32_t)n * 1536 + (uint32_t)((kb ^ (n & 7)) << 4);
        *reinterpret_cast<uint4*>(smem + dst) = *reinterpret_cast<const uint4*>(src);
    }
    float* cst = reinterpret_cast<float*>(smem + SB_CST);
    for (int i = tid; i < 1024; i += RTHREADS) {
        int b = i >> 3, jj = i & 7;
        cst[i] = g_ct[b * HSZ + j0 + jj];
    }
    float* stg = reinterpret_cast<float*>(smem + SB_STG);
    __syncthreads();

    const int mgrp = wid & 7, ngrp = wid >> 3;
    const int mb = mgrp * 16, nbW = ngrp * 16;
    const int pairLane = ngrp * 32 + lane;
    const int barId = 1 + mgrp;
    const int bL = tid >> 2, qL = tid & 3;

    float4 xv[2];
    {
        const float* xgp = g_xg + (size_t)bL * GSZ + n0 + qL * 8;
        xv[0] = __ldcg(reinterpret_cast<const float4*>(xgp));
        xv[1] = __ldcg(reinterpret_cast<const float4*>(xgp + 4));
    }

    for (int s = 0; s < Ss; s++) {
        issue_pairA(sb, mgrp, pairLane, 0, 0);
        issue_pairA(sb, mgrp, pairLane, 1, 1);

        float c[2][4] = {};
        for (int kc = 0; kc < 12; kc++) {
            if (kc < 11) CP_WAIT1(); else CP_WAIT0();
            BAR_PAIR(barId);
            if (kc < 10) issue_pairA(sb, mgrp, pairLane, kc + 2, (kc + 2) % 3);

            const uint32_t abuf = sb + SB_A + (uint32_t)(kc % 3) * 16384u;
#pragma unroll
            for (int ks2 = 0; ks2 < 4; ks2++) {
                uint32_t ah[4], bh[4];
                int kbA = ks2 * 2 + (lane >> 4);
                int rowA = mb + (lane & 15);
                uint32_t offA = abuf + (uint32_t)rowA * 128 + (uint32_t)((kbA ^ (rowA & 7)) << 4);
                ldsm4(ah[0], ah[1], ah[2], ah[3], offA);
                int rowB = nbW + ((lane >> 4) << 3) + (lane & 7);
                int kbB = kc * 8 + ks2 * 2 + ((lane >> 3) & 1);
                uint32_t offB = (uint32_t)rowB * 1536 + (uint32_t)((kbB ^ (rowB & 7)) << 4);
                ldsm4(bh[0], bh[1], bh[2], bh[3], SB_BHI + sb + offB);
                mma16816h(c[0], ah, bh[0], bh[1]);
                mma16816h(c[1], ah, bh[2], bh[3]);
            }
        }

        {
            int r0 = mb + (lane >> 2);
            int col0 = nbW + (lane & 3) * 2;
#pragma unroll
            for (int nj = 0; nj < 2; nj++) {
                int col = col0 + nj * 8;
                stg[r0 * 36 + col]           = c[nj][0];
                stg[r0 * 36 + col + 1]       = c[nj][1];
                stg[(r0 + 8) * 36 + col]     = c[nj][2];
                stg[(r0 + 8) * 36 + col + 1] = c[nj][3];
            }
        }
        __syncthreads();

        float hq[2], cq[2];
        {
            const float* sp = stg + bL * 36 + qL * 8;
#pragma unroll
            for (int q = 0; q < 2; q++) {
                float vi = xv[q].x + sp[q * 4 + 0];
                float vf = xv[q].y + sp[q * 4 + 1];
                float vg = xv[q].z + sp[q * 4 + 2];
                float vo = xv[q].w + sp[q * 4 + 3];
                float ig = fsig(vi), fg = fsig(vf), gg = ftanh(vg), og = fsig(vo);
                int ci = bL * 8 + qL * 2 + q;
                float cc = fg * cst[ci] + ig * gg;
                cst[ci] = cc;
                hq[q] = og * ftanh(cc);
                cq[q] = cc;
            }
            __half2 hh;
            hh.x = __float2half_rn(hq[0]);
            hh.y = __float2half_rn(hq[1]);
            *reinterpret_cast<__half2*>(g_Hf + bL * HSZ + j0 + qL * 2) = hh;
        }

        __syncthreads();
        if (tid == 0) {
            __threadfence();
            if (atomicAdd(&g_cnt, 1u) == NCTAR - 1u) {
                g_cnt = 0;
                __threadfence();
                g_epoch = (unsigned)(s + 1);
            }
        }
        {
            int hoff = bL * HSZ + j0 + qL * 2;
            float2 hv = make_float2(hq[0], hq[1]);
            *reinterpret_cast<float2*>(out + ((size_t)bL * Ss + s) * HSZ + j0 + qL * 2) = hv;
            if (s == Ss - 1) {
                *reinterpret_cast<float2*>(out + HID + hoff) = hv;
                *reinterpret_cast<float2*>(out + HID + STATE + hoff) = make_float2(cq[0], cq[1]);
            }
            if (s + 1 < Ss) {
                const float* xgp = g_xg + ((size_t)(s + 1) * Bb + bL) * GSZ + n0 + qL * 8;
                xv[0] = __ldcg(reinterpret_cast<const float4*>(xgp));
                xv[1] = __ldcg(reinterpret_cast<const float4*>(xgp + 4));
            }
        }
        if (tid == 0) {
            while (g_epoch <= (unsigned)s) { }
        }
        __syncthreads();
    }
}

extern "C" void kernel_launch(void* const* d_in, const int* in_sizes, int n_in,
                              void* d_out, int out_size) {
    const float* x    = (const float*)d_in[0];
    const float* h0   = (const float*)d_in[1];
    const float* c0   = (const float*)d_in[2];
    const float* W    = (const float*)d_in[3];
    const float* U    = (const float*)d_in[4];
    const float* bias = (const float*)d_in[5];
    const float* G    = (const float*)d_in[6];
    float* out = (float*)d_out;
    (void)in_sizes; (void)n_in; (void)out_size;

    cudaFuncSetAttribute(xw_gemm, cudaFuncAttributeMaxDynamicSharedMemorySize, SMEMX);
    cudaFuncSetAttribute(recur2,  cudaFuncAttributeMaxDynamicSharedMemorySize, SMEM2);

    convAll<<<(Bb * Ss * ISZ + 255) / 256, 256>>>(x, h0, c0, W, U, bias, G);
    xw_gemm<<<dim3(24, 128), 256, SMEMX>>>();
    dummyK<<<1, 1>>>();
    recur2<<<NCTAR, RTHREADS, SMEM2>>>(out);
}